// round 12
// baseline (speedup 1.0000x reference)
#include <cuda_runtime.h>
#include <cuda_bf16.h>
#include <cstdint>

#define NU 100000
#define NM 20000
#define DD 128
#define EE 1000000
#define CAPU 96    // >10 sigma above Poisson(10) max over 100k draws
#define CAPM 256   // >10 sigma above Poisson(50) max over 20k draws
#define TU 782     // ceil(NU/128)  (image tiles)
#define TM 157     // ceil(NM/128)
#define TU64 1563  // ceil(NU/64)   (fused-kernel tiles)
#define TM64 313   // ceil(NM/64)
#define BUILD_BLOCKS ((EE + 255) / 256)

// ---------------- scratch (static device globals; no runtime alloc) --------
__device__ int    g_deg_u[NU];
__device__ int    g_deg_m[NM];
__device__ int    g_csr_u[(size_t)NU * CAPU];
__device__ int    g_csr_m[(size_t)NM * CAPM];
__device__ float4 g_r_u[NU * 32];              // layer-1 output (fp32, for layer-2 gather)
__device__ float4 g_r_m[NM * 32];
// bf16 hi/lo images, per 128-row tile = 64KB laid out as 4 16KB planes:
// [kh0 hi][kh0 lo][kh1 hi][kh1 lo]; within a plane value (row, klocal) at
// byte swz128(row*128 + klocal*2).
__device__ uint4 g_ix_u[(size_t)TU * 4096];    // x_user image
__device__ uint4 g_ix_m[(size_t)TM * 4096];    // x_movie image
__device__ uint4 g_ir_u[(size_t)TU * 4096];    // layer-1 output image
__device__ uint4 g_ir_m[(size_t)TM * 4096];
// Pre-built mma B fragments, hi/lo MERGED: [matrix][kc][ntile][lane] =
// {hi.k0pair, hi.k8pair, lo.k0pair, lo.k8pair} (canonical m16n8k16 B layout).
__device__ uint4 g_Bfrag[8][8][16][32];

// ---------------- helpers ---------------------------------------------------
__device__ __forceinline__ uint32_t smem_u32(const void* p) {
    uint32_t a;
    asm("{ .reg .u64 t; cvta.to.shared.u64 t, %1; cvt.u32.u64 %0, t; }" : "=r"(a) : "l"(p));
    return a;
}
__device__ __forceinline__ uint32_t pk_bf16x2(float a, float b) {   // {lo=a, hi=b}
    uint32_t r;
    asm("cvt.rn.bf16x2.f32 %0, %1, %2;" : "=r"(r) : "f"(b), "f"(a));
    return r;
}
__device__ __forceinline__ void ldm4(uint32_t* r, uint32_t addr) {
    asm volatile("ldmatrix.sync.aligned.m8n8.x4.shared.b16 {%0,%1,%2,%3}, [%4];"
                 : "=r"(r[0]), "=r"(r[1]), "=r"(r[2]), "=r"(r[3]) : "r"(addr));
}
__device__ __forceinline__ void mma16816(float* c, const uint32_t* a, uint32_t b0, uint32_t b1) {
    asm volatile("mma.sync.aligned.m16n8k16.row.col.f32.bf16.bf16.f32 "
                 "{%0,%1,%2,%3}, {%4,%5,%6,%7}, {%8,%9}, {%0,%1,%2,%3};"
                 : "+f"(c[0]), "+f"(c[1]), "+f"(c[2]), "+f"(c[3])
                 : "r"(a[0]), "r"(a[1]), "r"(a[2]), "r"(a[3]), "r"(b0), "r"(b1));
}
#define CP_ASYNC16(dst, src) asm volatile("cp.async.cg.shared.global [%0], [%1], 16;" :: "r"(dst), "l"(src))
#define CP_COMMIT()          asm volatile("cp.async.commit_group;" ::: "memory")
#define CP_WAIT0()           asm volatile("cp.async.wait_group 0;" ::: "memory")
// swizzle for 128B rows: XOR 16B-chunk bits [4:7) with (row & 7)
__device__ __forceinline__ uint32_t swz128(uint32_t off) { return off ^ ((off >> 3) & 0x70u); }

// ---------------- fused CSR build + xprep ------------------------------------
__global__ __launch_bounds__(256) void build_xprep_kernel(
    const int* __restrict__ src, const int* __restrict__ dst,
    const float* __restrict__ xu, const float* __restrict__ xm)
{
    if ((int)blockIdx.x < BUILD_BLOCKS) {
        int e = blockIdx.x * 256 + threadIdx.x;
        if (e >= EE) return;
        int s = __ldg(src + e);
        int d = __ldg(dst + e);
        int pm = atomicAdd(&g_deg_m[d], 1);
        if (pm < CAPM) g_csr_m[(size_t)d * CAPM + pm] = s;
        int pu = atomicAdd(&g_deg_u[s], 1);
        if (pu < CAPU) g_csr_u[(size_t)s * CAPU + pu] = d;
        return;
    }
    int b = blockIdx.x - BUILD_BLOCKS;
    const bool user = b < TU;
    const int t = user ? b : b - TU;
    const int M = user ? NU : NM;
    const float* X = user ? xu : xm;
    char* img = (char*)((user ? g_ix_u : g_ix_m) + (size_t)t * 4096);

    for (int g = threadIdx.x; g < 2048; g += 256) {
        int row = g >> 4;
        int k = (g & 15) * 8;
        int grow = t * 128 + row;
        if (grow > M - 1) grow = M - 1;
        const float4* src4 = (const float4*)&X[(size_t)grow * 128 + k];
        float4 v0 = __ldg(src4), v1 = __ldg(src4 + 1);
        uint4 hi, lo;
        hi.x = pk_bf16x2(v0.x, v0.y);
        hi.y = pk_bf16x2(v0.z, v0.w);
        hi.z = pk_bf16x2(v1.x, v1.y);
        hi.w = pk_bf16x2(v1.z, v1.w);
        lo.x = pk_bf16x2(v0.x - __uint_as_float(hi.x << 16), v0.y - __uint_as_float(hi.x & 0xFFFF0000u));
        lo.y = pk_bf16x2(v0.z - __uint_as_float(hi.y << 16), v0.w - __uint_as_float(hi.y & 0xFFFF0000u));
        lo.z = pk_bf16x2(v1.x - __uint_as_float(hi.z << 16), v1.y - __uint_as_float(hi.z & 0xFFFF0000u));
        lo.w = pk_bf16x2(v1.z - __uint_as_float(hi.w << 16), v1.w - __uint_as_float(hi.w & 0xFFFF0000u));
        char* plane = img + (k >> 6) * 32768;
        uint32_t so = swz128((uint32_t)row * 128u + (uint32_t)(k & 63) * 2u);
        *(uint4*)(plane + so) = hi;
        *(uint4*)(plane + 16384 + so) = lo;
    }
}

// ---------------- weight prep: canonical B fragments, hi/lo merged ----------
__global__ __launch_bounds__(256) void prep_kernel(
    const float* __restrict__ W0, const float* __restrict__ W1,
    const float* __restrict__ W2, const float* __restrict__ W3,
    const float* __restrict__ W4, const float* __restrict__ W5,
    const float* __restrict__ W6, const float* __restrict__ W7)
{
    const float* Ws[8] = {W0, W1, W2, W3, W4, W5, W6, W7};
    int m = blockIdx.x;
    const float* W = Ws[m];
    for (int idx = threadIdx.x; idx < 4096; idx += 256) {
        int kc = idx >> 9;
        int t = (idx >> 5) & 15;
        int lane = idx & 31;
        int n = t * 8 + (lane >> 2);
        int k0 = kc * 16 + (lane & 3) * 2;
        float w00 = __ldg(&W[(size_t)k0 * 128 + n]);
        float w01 = __ldg(&W[(size_t)(k0 + 1) * 128 + n]);
        float w10 = __ldg(&W[(size_t)(k0 + 8) * 128 + n]);
        float w11 = __ldg(&W[(size_t)(k0 + 9) * 128 + n]);
        uint32_t h0 = pk_bf16x2(w00, w01);
        uint32_t h1 = pk_bf16x2(w10, w11);
        uint32_t l0 = pk_bf16x2(w00 - __uint_as_float(h0 << 16), w01 - __uint_as_float(h0 & 0xFFFF0000u));
        uint32_t l1 = pk_bf16x2(w10 - __uint_as_float(h1 << 16), w11 - __uint_as_float(h1 & 0xFFFF0000u));
        g_Bfrag[m][kc][t][lane] = make_uint4(h0, h1, l0, l1);
    }
}

// ---------------- fused gather + tensor GEMM --------------------------------
// CTA = 64-row x 128-col tile (movie tiles first). Per CTA:
//  1. cp.async the self-feature image sub-tile (pass-1 A) into smem
//  2. 8 warps gather 8 nodes each (fp32 mean) -> write hi/lo A tile in smem
//  3. one syncthreads; pass0 (agg@Wl) + pass1 (x@Wr) MMAs; epilogue.
// smem planes (8KB each): AGG[kh0hi,kh0lo,kh1hi,kh1lo], X[same]  (66KB total)
#define SM_BIAS 0
#define SM_AGG  1024
#define SM_X    (1024 + 32768)
#define SM_TOTAL (1024 + 65536)

__global__ __launch_bounds__(256, 3) void fused_kernel(
    const float4* __restrict__ fu, const float4* __restrict__ fm,   // gather src (fp32)
    const uint4* __restrict__ ixu, const uint4* __restrict__ ixm,   // self images
    const float* __restrict__ xres_u, const float* __restrict__ xres_m,
    const float* __restrict__ b_mu, const float* __restrict__ b_um,
    float* __restrict__ out_u, float* __restrict__ out_m,
    int mode, int layer)
{
    extern __shared__ char smem[];
    const uint32_t sb = smem_u32(smem);
    const int tid = threadIdx.x;
    const int wid = tid >> 5;
    const int lane = tid & 31;

    const bool movie = (int)blockIdx.x < TM64;
    const int t64 = movie ? blockIdx.x : blockIdx.x - TM64;
    const int base = t64 * 64;
    const int M = movie ? NM : NU;
    const float4* gsrc = movie ? fu : fm;          // movies gather user feats
    const int* csr = movie ? g_csr_m : g_csr_u;
    const int* degA = movie ? g_deg_m : g_deg_u;
    const int cap = movie ? CAPM : CAPU;
    const uint4* img = (movie ? ixm : ixu) + (size_t)(t64 >> 1) * 4096;
    const int half = t64 & 1;
    const float* xres = movie ? xres_m : xres_u;
    const float* bias = movie ? b_um : b_mu;
    float* out = movie ? out_m : out_u;
    float* rfp = (float*)(movie ? g_r_m : g_r_u);
    char* irout = (char*)((movie ? g_ir_m : g_ir_u) + (size_t)(t64 >> 1) * 4096);
    const int wl_idx = (movie ? 0 : 2) + 4 * layer;
    const int wr_idx = wl_idx + 1;

    // 1. stage self-feature sub-tile (4 x 8KB planes) via cp.async
#pragma unroll
    for (int i = 0; i < 8; i++) {
        int f = tid + i * 256;                  // 0..2047 uint4
        int plane = f >> 9, within = f & 511;
        CP_ASYNC16(sb + SM_X + (uint32_t)f * 16u,
                   img + plane * 1024 + half * 512 + within);
    }
    CP_COMMIT();

    float* bsm = (float*)(smem + SM_BIAS);
    if (tid < 128) bsm[tid] = __ldg(&bias[tid]);

    // 2. gather: warp handles 8 nodes, mean of fp32 neighbor rows -> smem image
    for (int j = 0; j < 8; j++) {
        int lr = wid * 8 + j;
        int node = base + lr;
        if (node >= M) break;
        int deg = min(__ldg(&degA[node]), cap);
        const int* nl = &csr[(size_t)node * cap];

        float4 a0 = make_float4(0.f, 0.f, 0.f, 0.f);
        float4 a1 = make_float4(0.f, 0.f, 0.f, 0.f);
        for (int i = 0; i < deg; i += 32) {
            int idx = (i + lane < deg) ? __ldg(nl + i + lane) : 0;
            int cnt = min(32, deg - i);
            if (cnt == 32) {
#pragma unroll
                for (int q = 0; q < 32; q += 2) {
                    int i0 = __shfl_sync(0xffffffffu, idx, q);
                    int i1 = __shfl_sync(0xffffffffu, idx, q + 1);
                    float4 v0 = __ldg(&gsrc[(size_t)i0 * 32 + lane]);
                    float4 v1 = __ldg(&gsrc[(size_t)i1 * 32 + lane]);
                    a0.x += v0.x; a0.y += v0.y; a0.z += v0.z; a0.w += v0.w;
                    a1.x += v1.x; a1.y += v1.y; a1.z += v1.z; a1.w += v1.w;
                }
            } else {
                for (int q = 0; q < cnt; q++) {
                    int i0 = __shfl_sync(0xffffffffu, idx, q);
                    float4 v = __ldg(&gsrc[(size_t)i0 * 32 + lane]);
                    a0.x += v.x; a0.y += v.y; a0.z += v.z; a0.w += v.w;
                }
            }
        }
        float inv = 1.f / (float)max(deg, 1);
        float rx = (a0.x + a1.x) * inv, ry = (a0.y + a1.y) * inv;
        float rz = (a0.z + a1.z) * inv, rw = (a0.w + a1.w) * inv;

        uint2 hi, lo;
        hi.x = pk_bf16x2(rx, ry);
        hi.y = pk_bf16x2(rz, rw);
        lo.x = pk_bf16x2(rx - __uint_as_float(hi.x << 16), ry - __uint_as_float(hi.x & 0xFFFF0000u));
        lo.y = pk_bf16x2(rz - __uint_as_float(hi.y << 16), rw - __uint_as_float(hi.y & 0xFFFF0000u));
        char* plane = smem + SM_AGG + (lane >> 4) * 16384;
        uint32_t so = swz128((uint32_t)lr * 128u + (uint32_t)((lane * 8) & 127));
        *(uint2*)(plane + so) = hi;
        *(uint2*)(plane + 8192 + so) = lo;
    }

    CP_WAIT0();
    __syncthreads();    // agg smem + staged x + bias all ready

    // 3. MMAs: warp grid 2(M) x 4(N), warp tile 32x32
    const int wm = wid & 1, wn = wid >> 1;
    const int a_row = (lane & 7) + ((lane >> 3) & 1) * 8;
    const int a_kh  = ((lane >> 4) & 1) * 8;
    uint32_t aoff[2];
#pragma unroll
    for (int tm = 0; tm < 2; tm++)
        aoff[tm] = (uint32_t)(wm * 32 + tm * 16 + a_row) * 128u + (uint32_t)a_kh * 2u;

    float acc[2][4][4];
#pragma unroll
    for (int i = 0; i < 2; i++)
#pragma unroll
        for (int j = 0; j < 4; j++)
#pragma unroll
            for (int q = 0; q < 4; q++) acc[i][j][q] = 0.f;

#pragma unroll
    for (int pass = 0; pass < 2; pass++) {
        const int widx = pass ? wr_idx : wl_idx;
        const uint32_t pbase = sb + (pass ? SM_X : SM_AGG);
        const uint4* bf = &g_Bfrag[widx][0][wn * 4][lane];
#pragma unroll
        for (int kh = 0; kh < 2; kh++) {
            const uint32_t abase = pbase + (uint32_t)kh * 16384u;
#pragma unroll
            for (int kcl = 0; kcl < 4; kcl++) {
                const int kc = kh * 4 + kcl;
                uint32_t ah[2][4], al[2][4];
#pragma unroll
                for (int tm = 0; tm < 2; tm++) {
                    uint32_t so = swz128(aoff[tm] + (uint32_t)kcl * 32u);
                    ldm4(ah[tm], abase + so);
                    ldm4(al[tm], abase + 8192 + so);
                }
#pragma unroll
                for (int tn = 0; tn < 4; tn++) {
                    uint4 b = __ldg(bf + (size_t)kc * 512 + tn * 32);
#pragma unroll
                    for (int tm = 0; tm < 2; tm++) {
                        mma16816(acc[tm][tn], ah[tm], b.x, b.y);
                        mma16816(acc[tm][tn], ah[tm], b.z, b.w);
                        mma16816(acc[tm][tn], al[tm], b.x, b.y);
                    }
                }
            }
        }
    }

    // 4. epilogue
    const int gid = lane >> 2, qid = lane & 3;
#pragma unroll
    for (int tm = 0; tm < 2; tm++) {
#pragma unroll
        for (int rs = 0; rs < 2; rs++) {
            int lrow = wm * 32 + tm * 16 + gid + rs * 8;
            int row = base + lrow;
            if (row < M) {
#pragma unroll
                for (int tn = 0; tn < 4; tn++) {
                    int col = wn * 32 + tn * 8 + qid * 2;
                    float vx = acc[tm][tn][rs * 2 + 0] + bsm[col];
                    float vy = acc[tm][tn][rs * 2 + 1] + bsm[col + 1];
                    if (mode) {
                        float2 xv = __ldg((const float2*)&xres[(size_t)row * 128 + col]);
                        vx = xv.x + fmaxf(vx, 0.f);
                        vy = xv.y + fmaxf(vy, 0.f);
                        *(float2*)&rfp[(size_t)row * 128 + col] = make_float2(vx, vy);
                        uint32_t hv = pk_bf16x2(vx, vy);
                        uint32_t lv = pk_bf16x2(vx - __uint_as_float(hv << 16),
                                                vy - __uint_as_float(hv & 0xFFFF0000u));
                        char* plane = irout + (col >> 6) * 32768;
                        uint32_t rowIn128 = (uint32_t)(half * 64 + lrow);
                        uint32_t so = swz128(rowIn128 * 128u + (uint32_t)(col & 63) * 2u);
                        *(uint32_t*)(plane + so) = hv;
                        *(uint32_t*)(plane + 16384 + so) = lv;
                    } else {
                        *(float2*)&out[(size_t)row * 128 + col] = make_float2(vx, vy);
                    }
                }
            }
        }
    }
}

// ---------------- host ------------------------------------------------------
extern "C" void kernel_launch(void* const* d_in, const int* in_sizes, int n_in,
                              void* d_out, int out_size)
{
    const float* x_user = nullptr;
    const float* x_movie = nullptr;
    const int* e_src = nullptr;
    const int* e_dst = nullptr;
    const float* W[8] = {};
    const float* B[4] = {};
    int nw = 0, nb = 0;
    for (int i = 0; i < n_in; i++) {
        int sz = in_sizes[i];
        if (sz == NU * DD)      x_user = (const float*)d_in[i];
        else if (sz == NM * DD) x_movie = (const float*)d_in[i];
        else if (sz == EE)      { if (!e_src) e_src = (const int*)d_in[i]; else e_dst = (const int*)d_in[i]; }
        else if (sz == DD * DD) { if (nw < 8) W[nw++] = (const float*)d_in[i]; }
        else if (sz == DD)      { if (nb < 4) B[nb++] = (const float*)d_in[i]; }
    }
    // W order: Wl1_um, Wr1_um, Wl1_mu, Wr1_mu, Wl2_um, Wr2_um, Wl2_mu, Wr2_mu
    const float *b1_um = B[0], *b1_mu = B[1], *b2_um = B[2], *b2_mu = B[3];

    float* out = (float*)d_out;
    int *deg_u, *deg_m;
    float *r_u, *r_m;
    uint4 *ix_u, *ix_m, *ir_u, *ir_m;
    cudaGetSymbolAddress((void**)&deg_u, g_deg_u);
    cudaGetSymbolAddress((void**)&deg_m, g_deg_m);
    cudaGetSymbolAddress((void**)&r_u, g_r_u);
    cudaGetSymbolAddress((void**)&r_m, g_r_m);
    cudaGetSymbolAddress((void**)&ix_u, g_ix_u);
    cudaGetSymbolAddress((void**)&ix_m, g_ix_m);
    cudaGetSymbolAddress((void**)&ir_u, g_ir_u);
    cudaGetSymbolAddress((void**)&ir_m, g_ir_m);

    cudaFuncSetAttribute(fused_kernel, cudaFuncAttributeMaxDynamicSharedMemorySize, SM_TOTAL);

    prep_kernel<<<8, 256>>>(W[0], W[1], W[2], W[3], W[4], W[5], W[6], W[7]);

    // CSR build + x image prep fused (CSR reused by both layers)
    cudaMemsetAsync(deg_u, 0, NU * sizeof(int));
    cudaMemsetAsync(deg_m, 0, NM * sizeof(int));
    build_xprep_kernel<<<BUILD_BLOCKS + TU + TM, 256>>>(e_src, e_dst, x_user, x_movie);

    const int grid = TM64 + TU64;

    // Layer 1: gather from x (fp32) + gemm -> r (fp32 + image)
    fused_kernel<<<grid, 256, SM_TOTAL>>>((const float4*)x_user, (const float4*)x_movie,
                                          ix_u, ix_m, x_user, x_movie,
                                          b1_mu, b1_um, nullptr, nullptr, 1, 0);

    // Layer 2: gather from r (fp32) + gemm -> fp32 d_out
    fused_kernel<<<grid, 256, SM_TOTAL>>>((const float4*)r_u, (const float4*)r_m,
                                          ir_u, ir_m, nullptr, nullptr,
                                          b2_mu, b2_um, out, out + (size_t)NU * DD, 0, 1);
}

// round 13
// speedup vs baseline: 1.0622x; 1.0622x over previous
#include <cuda_runtime.h>
#include <cuda_bf16.h>
#include <cstdint>

#define NU 100000
#define NM 20000
#define DD 128
#define EE 1000000
#define CAPU 96    // >10 sigma above Poisson(10) max over 100k draws
#define CAPM 256   // >10 sigma above Poisson(50) max over 20k draws
#define TU 782     // ceil(NU/128)
#define TM 157     // ceil(NM/128)
#define BUILD_BLOCKS ((EE + 255) / 256)

// ---------------- scratch (static device globals; no runtime alloc) --------
__device__ int    g_deg_u[NU];
__device__ int    g_deg_m[NM];
__device__ int    g_csr_u[(size_t)NU * CAPU];
__device__ int    g_csr_m[(size_t)NM * CAPM];
__device__ float4 g_r_u[NU * 32];              // layer-1 output (fp32, for gather2)
__device__ float4 g_r_m[NM * 32];
// bf16 hi/lo images, per 128-row tile = 64KB laid out as
// [khalf0: hi 16KB | lo 16KB][khalf1: hi 16KB | lo 16KB];
// within a 16KB plane value (row, klocal) at byte swz128(row*128 + klocal*2).
__device__ uint4 g_ix_u[(size_t)TU * 4096];    // x_user image
__device__ uint4 g_ix_m[(size_t)TM * 4096];    // x_movie image
__device__ uint4 g_iagg_u[(size_t)TU * 4096];  // agg at users
__device__ uint4 g_iagg_m[(size_t)TM * 4096];  // agg at movies
__device__ uint4 g_ir_u[(size_t)TU * 4096];    // layer-1 output image
__device__ uint4 g_ir_m[(size_t)TM * 4096];
// Pre-built mma B fragments, hi/lo MERGED: [matrix][kc][ntile][lane] =
// {hi.k0pair, hi.k8pair, lo.k0pair, lo.k8pair} (canonical m16n8k16 B layout).
__device__ uint4 g_Bfrag[8][8][16][32];

// ---------------- helpers ---------------------------------------------------
__device__ __forceinline__ uint32_t smem_u32(const void* p) {
    uint32_t a;
    asm("{ .reg .u64 t; cvta.to.shared.u64 t, %1; cvt.u32.u64 %0, t; }" : "=r"(a) : "l"(p));
    return a;
}
__device__ __forceinline__ uint32_t pk_bf16x2(float a, float b) {   // {lo=a, hi=b}
    uint32_t r;
    asm("cvt.rn.bf16x2.f32 %0, %1, %2;" : "=r"(r) : "f"(b), "f"(a));
    return r;
}
__device__ __forceinline__ void ldm4(uint32_t* r, uint32_t addr) {
    asm volatile("ldmatrix.sync.aligned.m8n8.x4.shared.b16 {%0,%1,%2,%3}, [%4];"
                 : "=r"(r[0]), "=r"(r[1]), "=r"(r[2]), "=r"(r[3]) : "r"(addr));
}
__device__ __forceinline__ void mma16816(float* c, const uint32_t* a, uint32_t b0, uint32_t b1) {
    asm volatile("mma.sync.aligned.m16n8k16.row.col.f32.bf16.bf16.f32 "
                 "{%0,%1,%2,%3}, {%4,%5,%6,%7}, {%8,%9}, {%0,%1,%2,%3};"
                 : "+f"(c[0]), "+f"(c[1]), "+f"(c[2]), "+f"(c[3])
                 : "r"(a[0]), "r"(a[1]), "r"(a[2]), "r"(a[3]), "r"(b0), "r"(b1));
}
#define CP_ASYNC16(dst, src) asm volatile("cp.async.cg.shared.global [%0], [%1], 16;" :: "r"(dst), "l"(src))
#define CP_COMMIT()          asm volatile("cp.async.commit_group;" ::: "memory")
#define CP_WAIT1()           asm volatile("cp.async.wait_group 1;" ::: "memory")
#define CP_WAIT0()           asm volatile("cp.async.wait_group 0;" ::: "memory")
// swizzle for 128B rows: XOR 16B-chunk bits [4:7) with (row & 7)
__device__ __forceinline__ uint32_t swz128(uint32_t off) { return off ^ ((off >> 3) & 0x70u); }

// ---------------- fused CSR build + xprep ------------------------------------
__global__ __launch_bounds__(256) void build_xprep_kernel(
    const int* __restrict__ src, const int* __restrict__ dst,
    const float* __restrict__ xu, const float* __restrict__ xm)
{
    if ((int)blockIdx.x < BUILD_BLOCKS) {
        int e = blockIdx.x * 256 + threadIdx.x;
        if (e >= EE) return;
        int s = __ldg(src + e);
        int d = __ldg(dst + e);
        int pm = atomicAdd(&g_deg_m[d], 1);
        if (pm < CAPM) g_csr_m[(size_t)d * CAPM + pm] = s;
        int pu = atomicAdd(&g_deg_u[s], 1);
        if (pu < CAPU) g_csr_u[(size_t)s * CAPU + pu] = d;
        return;
    }
    int b = blockIdx.x - BUILD_BLOCKS;
    const bool user = b < TU;
    const int t = user ? b : b - TU;
    const int M = user ? NU : NM;
    const float* X = user ? xu : xm;
    char* img = (char*)((user ? g_ix_u : g_ix_m) + (size_t)t * 4096);

    for (int g = threadIdx.x; g < 2048; g += 256) {
        int row = g >> 4;
        int k = (g & 15) * 8;
        int grow = t * 128 + row;
        if (grow > M - 1) grow = M - 1;
        const float4* src4 = (const float4*)&X[(size_t)grow * 128 + k];
        float4 v0 = __ldg(src4), v1 = __ldg(src4 + 1);
        uint4 hi, lo;
        hi.x = pk_bf16x2(v0.x, v0.y);
        hi.y = pk_bf16x2(v0.z, v0.w);
        hi.z = pk_bf16x2(v1.x, v1.y);
        hi.w = pk_bf16x2(v1.z, v1.w);
        lo.x = pk_bf16x2(v0.x - __uint_as_float(hi.x << 16), v0.y - __uint_as_float(hi.x & 0xFFFF0000u));
        lo.y = pk_bf16x2(v0.z - __uint_as_float(hi.y << 16), v0.w - __uint_as_float(hi.y & 0xFFFF0000u));
        lo.z = pk_bf16x2(v1.x - __uint_as_float(hi.z << 16), v1.y - __uint_as_float(hi.z & 0xFFFF0000u));
        lo.w = pk_bf16x2(v1.z - __uint_as_float(hi.w << 16), v1.w - __uint_as_float(hi.w & 0xFFFF0000u));
        char* plane = img + (k >> 6) * 32768;
        uint32_t so = swz128((uint32_t)row * 128u + (uint32_t)(k & 63) * 2u);
        *(uint4*)(plane + so) = hi;
        *(uint4*)(plane + 16384 + so) = lo;
    }
}

// ---------------- gather: mean of neighbor fp32 rows -> hi/lo image ---------
// One warp per node. Full chunks: 16x2 unrolled. Tail: x8 unrolled predicated
// loads (8 LDGs in flight) — user nodes (deg~10) live entirely on this path.
__global__ __launch_bounds__(256, 6) void gather_kernel(
    const float4* __restrict__ xu, const float4* __restrict__ xm)
{
    const int lane = threadIdx.x & 31;
    const int w = (blockIdx.x * 256 + threadIdx.x) >> 5;

    const int* csr;
    const float4* src;
    char* outImg;
    int deg, row;
    if (w < NU) {
        deg = min(__ldg(&g_deg_u[w]), CAPU);
        csr = &g_csr_u[(size_t)w * CAPU];
        src = xm;
        outImg = (char*)(g_iagg_u + (size_t)(w >> 7) * 4096);
        row = w & 127;
    } else {
        int n = w - NU;
        if (n >= NM) return;
        deg = min(__ldg(&g_deg_m[n]), CAPM);
        csr = &g_csr_m[(size_t)n * CAPM];
        src = xu;
        outImg = (char*)(g_iagg_m + (size_t)(n >> 7) * 4096);
        row = n & 127;
    }

    float4 a0 = make_float4(0.f, 0.f, 0.f, 0.f);
    float4 a1 = make_float4(0.f, 0.f, 0.f, 0.f);

    for (int i = 0; i < deg; i += 32) {
        int idx = (i + lane < deg) ? __ldg(csr + i + lane) : 0;
        int cnt = min(32, deg - i);
        if (cnt == 32) {
#pragma unroll
            for (int j = 0; j < 32; j += 2) {
                int i0 = __shfl_sync(0xffffffffu, idx, j);
                int i1 = __shfl_sync(0xffffffffu, idx, j + 1);
                float4 v0 = __ldg(&src[(size_t)i0 * 32 + lane]);
                float4 v1 = __ldg(&src[(size_t)i1 * 32 + lane]);
                a0.x += v0.x; a0.y += v0.y; a0.z += v0.z; a0.w += v0.w;
                a1.x += v1.x; a1.y += v1.y; a1.z += v1.z; a1.w += v1.w;
            }
        } else {
            for (int q = 0; q < cnt; q += 8) {
#pragma unroll
                for (int u = 0; u < 8; u++) {
                    if (q + u < cnt) {
                        int id = __shfl_sync(0xffffffffu, idx, q + u);
                        float4 v = __ldg(&src[(size_t)id * 32 + lane]);
                        if (u & 1) {
                            a1.x += v.x; a1.y += v.y; a1.z += v.z; a1.w += v.w;
                        } else {
                            a0.x += v.x; a0.y += v.y; a0.z += v.z; a0.w += v.w;
                        }
                    }
                }
            }
        }
    }
    float inv = 1.f / (float)max(deg, 1);
    float4 r;
    r.x = (a0.x + a1.x) * inv;
    r.y = (a0.y + a1.y) * inv;
    r.z = (a0.z + a1.z) * inv;
    r.w = (a0.w + a1.w) * inv;

    uint2 hi, lo;
    hi.x = pk_bf16x2(r.x, r.y);
    hi.y = pk_bf16x2(r.z, r.w);
    lo.x = pk_bf16x2(r.x - __uint_as_float(hi.x << 16), r.y - __uint_as_float(hi.x & 0xFFFF0000u));
    lo.y = pk_bf16x2(r.z - __uint_as_float(hi.y << 16), r.w - __uint_as_float(hi.y & 0xFFFF0000u));
    char* plane = outImg + (lane >> 4) * 32768;
    uint32_t so = swz128((uint32_t)row * 128u + (uint32_t)((lane * 8) & 127));
    *(uint2*)(plane + so) = hi;
    *(uint2*)(plane + 16384 + so) = lo;
}

// ---------------- weight prep: canonical B fragments, hi/lo merged ----------
__global__ __launch_bounds__(256) void prep_kernel(
    const float* __restrict__ W0, const float* __restrict__ W1,
    const float* __restrict__ W2, const float* __restrict__ W3,
    const float* __restrict__ W4, const float* __restrict__ W5,
    const float* __restrict__ W6, const float* __restrict__ W7)
{
    const float* Ws[8] = {W0, W1, W2, W3, W4, W5, W6, W7};
    int m = blockIdx.x;
    const float* W = Ws[m];
    for (int idx = threadIdx.x; idx < 4096; idx += 256) {
        int kc = idx >> 9;
        int t = (idx >> 5) & 15;
        int lane = idx & 31;
        int n = t * 8 + (lane >> 2);
        int k0 = kc * 16 + (lane & 3) * 2;
        float w00 = __ldg(&W[(size_t)k0 * 128 + n]);
        float w01 = __ldg(&W[(size_t)(k0 + 1) * 128 + n]);
        float w10 = __ldg(&W[(size_t)(k0 + 8) * 128 + n]);
        float w11 = __ldg(&W[(size_t)(k0 + 9) * 128 + n]);
        uint32_t h0 = pk_bf16x2(w00, w01);
        uint32_t h1 = pk_bf16x2(w10, w11);
        uint32_t l0 = pk_bf16x2(w00 - __uint_as_float(h0 << 16), w01 - __uint_as_float(h0 & 0xFFFF0000u));
        uint32_t l1 = pk_bf16x2(w10 - __uint_as_float(h1 << 16), w11 - __uint_as_float(h1 & 0xFFFF0000u));
        g_Bfrag[m][kc][t][lane] = make_uint4(h0, h1, l0, l1);
    }
}

// ---------------- tensor GEMM: 128x64 CTA tile, 3 CTAs/SM -------------------
// bid = 2*tile + nhalf. 8 warps as 4(M) x 2(N); warp tile 32x32 (acc 32 regs).
// Adjacent CTA pairs share the A tile (L2 reuse). cp.async 2-deep pipeline.
// mode 1: residual x is read from the staged smem image (hi+lo), not global.
#define SM_BIAS 0
#define SM_A    1024
#define SM_TOTAL (1024 + 65536)

__global__ __launch_bounds__(256, 3) void tgemm_kernel(
    const uint4* __restrict__ ia0_u, const uint4* __restrict__ ia0_m,
    const uint4* __restrict__ ia1_u, const uint4* __restrict__ ia1_m,
    const float* __restrict__ b_mu, const float* __restrict__ b_um,
    float* __restrict__ out_u, float* __restrict__ out_m,
    int gb_u, int mode, int layer)
{
    extern __shared__ char smem[];
    const uint32_t sb = smem_u32(smem);
    const int tid = threadIdx.x;
    const int wid = tid >> 5;
    const int lane = tid & 31;

    const int tileg = blockIdx.x >> 1;           // global tile index
    const int nhalf = blockIdx.x & 1;            // which 64-col half
    const bool user = tileg < gb_u;
    const int  tile = user ? tileg : tileg - gb_u;
    const int  base = tile * 128;
    const int  M    = user ? NU : NM;
    const uint4* ia0 = (user ? ia0_u : ia0_m) + (size_t)tile * 4096;  // agg image
    const uint4* ia1 = (user ? ia1_u : ia1_m) + (size_t)tile * 4096;  // x/r image
    const float* bias = user ? b_mu : b_um;
    float* out = user ? out_u : out_m;
    float* rfp = (float*)(user ? g_r_u : g_r_m);
    char* irout = (char*)((user ? g_ir_u : g_ir_m) + (size_t)tile * 4096);
    const int wl_idx = (user ? 2 : 0) + 4 * layer;
    const int wr_idx = wl_idx + 1;

    float* bsm = (float*)(smem + SM_BIAS);
    if (tid < 128) bsm[tid] = __ldg(&bias[tid]);

    const int wm = wid & 3, wn = wid >> 2;       // 4 x 2 warp grid
    const int tbase = nhalf * 8 + wn * 4;        // B ntile base for this warp

    // seg s: pass = s>>1, khalf = s&1 ; source = 32KB at image + khalf*2048 uint4
    auto issue_seg = [&](int s) {
        const uint4* src = ((s >> 1) ? ia1 : ia0) + (s & 1) * 2048;
        const uint32_t dbase = sb + SM_A + (uint32_t)(s & 1) * 32768u + (uint32_t)tid * 16u;
#pragma unroll
        for (int i = 0; i < 8; i++)
            CP_ASYNC16(dbase + (uint32_t)i * 4096u, src + tid + i * 256);
        CP_COMMIT();
    };

    // per-lane ldmatrix A offsets within a 16KB plane (pre-swizzle):
    const int a_row = (lane & 7) + ((lane >> 3) & 1) * 8;
    const int a_kh  = ((lane >> 4) & 1) * 8;
    uint32_t aoff[2];
#pragma unroll
    for (int tm = 0; tm < 2; tm++)
        aoff[tm] = (uint32_t)(wm * 32 + tm * 16 + a_row) * 128u + (uint32_t)a_kh * 2u;

    float acc[2][4][4];
#pragma unroll
    for (int i = 0; i < 2; i++)
#pragma unroll
        for (int j = 0; j < 4; j++)
#pragma unroll
            for (int q = 0; q < 4; q++) acc[i][j][q] = 0.f;

    issue_seg(0);
    issue_seg(1);

    for (int seg = 0; seg < 4; seg++) {
        if (seg < 3) CP_WAIT1(); else CP_WAIT0();
        __syncthreads();

        const int pass = seg >> 1, h = seg & 1;
        const int widx = pass ? wr_idx : wl_idx;
        const uint32_t abase = sb + SM_A + (uint32_t)h * 32768u;
        const uint4* bf = &g_Bfrag[widx][0][tbase][lane];

#pragma unroll
        for (int kcl = 0; kcl < 4; kcl++) {
            const int kc = h * 4 + kcl;
            uint32_t ah[2][4], al[2][4];
#pragma unroll
            for (int tm = 0; tm < 2; tm++) {
                uint32_t so = swz128(aoff[tm] + (uint32_t)kcl * 32u);
                ldm4(ah[tm], abase + so);
                ldm4(al[tm], abase + 16384 + so);
            }
#pragma unroll
            for (int tn = 0; tn < 4; tn++) {
                uint4 b = __ldg(bf + (size_t)kc * 512 + tn * 32);
#pragma unroll
                for (int tm = 0; tm < 2; tm++) {
                    mma16816(acc[tm][tn], ah[tm], b.x, b.y);
                    mma16816(acc[tm][tn], ah[tm], b.z, b.w);
                    mma16816(acc[tm][tn], al[tm], b.x, b.y);
                }
            }
        }
        __syncthreads();
        if (seg < 2) issue_seg(seg + 2);
    }
    // After the loop: buf0 = pass1 khalf0 (k 0..63), buf1 = pass1 khalf1.
    // mode-1 residual x is reconstructed (hi+lo) from these buffers.

    // ---- epilogue ----
    const int gid = lane >> 2, qid = lane & 3;
#pragma unroll
    for (int tm = 0; tm < 2; tm++) {
#pragma unroll
        for (int rs = 0; rs < 2; rs++) {
            int lrow = wm * 32 + tm * 16 + gid + rs * 8;
            int row = base + lrow;
            if (row < M) {
#pragma unroll
                for (int tn = 0; tn < 4; tn++) {
                    int col = nhalf * 64 + wn * 32 + tn * 8 + qid * 2;
                    float vx = acc[tm][tn][rs * 2 + 0] + bsm[col];
                    float vy = acc[tm][tn][rs * 2 + 1] + bsm[col + 1];
                    if (mode) {
                        char* xbuf = smem + SM_A + (col >> 6) * 32768;
                        uint32_t xso = swz128((uint32_t)lrow * 128u + (uint32_t)(col & 63) * 2u);
                        uint32_t xh = *(uint32_t*)(xbuf + xso);
                        uint32_t xl = *(uint32_t*)(xbuf + 16384 + xso);
                        float xvx = __uint_as_float(xh << 16) + __uint_as_float(xl << 16);
                        float xvy = __uint_as_float(xh & 0xFFFF0000u) + __uint_as_float(xl & 0xFFFF0000u);
                        vx = xvx + fmaxf(vx, 0.f);
                        vy = xvy + fmaxf(vy, 0.f);
                        *(float2*)&rfp[(size_t)row * 128 + col] = make_float2(vx, vy);
                        uint32_t hv = pk_bf16x2(vx, vy);
                        uint32_t lv = pk_bf16x2(vx - __uint_as_float(hv << 16),
                                                vy - __uint_as_float(hv & 0xFFFF0000u));
                        char* plane = irout + (col >> 6) * 32768;
                        uint32_t so = swz128((uint32_t)lrow * 128u + (uint32_t)(col & 63) * 2u);
                        *(uint32_t*)(plane + so) = hv;
                        *(uint32_t*)(plane + 16384 + so) = lv;
                    } else {
                        *(float2*)&out[(size_t)row * 128 + col] = make_float2(vx, vy);
                    }
                }
            }
        }
    }
}

// ---------------- host ------------------------------------------------------
extern "C" void kernel_launch(void* const* d_in, const int* in_sizes, int n_in,
                              void* d_out, int out_size)
{
    const float* x_user = nullptr;
    const float* x_movie = nullptr;
    const int* e_src = nullptr;
    const int* e_dst = nullptr;
    const float* W[8] = {};
    const float* B[4] = {};
    int nw = 0, nb = 0;
    for (int i = 0; i < n_in; i++) {
        int sz = in_sizes[i];
        if (sz == NU * DD)      x_user = (const float*)d_in[i];
        else if (sz == NM * DD) x_movie = (const float*)d_in[i];
        else if (sz == EE)      { if (!e_src) e_src = (const int*)d_in[i]; else e_dst = (const int*)d_in[i]; }
        else if (sz == DD * DD) { if (nw < 8) W[nw++] = (const float*)d_in[i]; }
        else if (sz == DD)      { if (nb < 4) B[nb++] = (const float*)d_in[i]; }
    }
    // W order: Wl1_um, Wr1_um, Wl1_mu, Wr1_mu, Wl2_um, Wr2_um, Wl2_mu, Wr2_mu
    const float *b1_um = B[0], *b1_mu = B[1], *b2_um = B[2], *b2_mu = B[3];

    float* out = (float*)d_out;
    int *deg_u, *deg_m;
    float *r_u, *r_m;
    uint4 *ix_u, *ix_m, *iagg_u, *iagg_m, *ir_u, *ir_m;
    cudaGetSymbolAddress((void**)&deg_u, g_deg_u);
    cudaGetSymbolAddress((void**)&deg_m, g_deg_m);
    cudaGetSymbolAddress((void**)&r_u, g_r_u);
    cudaGetSymbolAddress((void**)&r_m, g_r_m);
    cudaGetSymbolAddress((void**)&ix_u, g_ix_u);
    cudaGetSymbolAddress((void**)&ix_m, g_ix_m);
    cudaGetSymbolAddress((void**)&iagg_u, g_iagg_u);
    cudaGetSymbolAddress((void**)&iagg_m, g_iagg_m);
    cudaGetSymbolAddress((void**)&ir_u, g_ir_u);
    cudaGetSymbolAddress((void**)&ir_m, g_ir_m);

    cudaFuncSetAttribute(tgemm_kernel, cudaFuncAttributeMaxDynamicSharedMemorySize, SM_TOTAL);

    const int gblocks = (NU + NM) / 8;          // one warp per node

    prep_kernel<<<8, 256>>>(W[0], W[1], W[2], W[3], W[4], W[5], W[6], W[7]);

    // CSR build + x image prep fused (CSR reused by both layers)
    cudaMemsetAsync(deg_u, 0, NU * sizeof(int));
    cudaMemsetAsync(deg_m, 0, NM * sizeof(int));
    build_xprep_kernel<<<BUILD_BLOCKS + TU + TM, 256>>>(e_src, e_dst, x_user, x_movie);

    // Layer 1: gather fp32 x -> agg image; gemm -> r (fp32 + image)
    gather_kernel<<<gblocks, 256>>>((const float4*)x_user, (const float4*)x_movie);
    tgemm_kernel<<<2 * (TU + TM), 256, SM_TOTAL>>>(iagg_u, iagg_m, ix_u, ix_m,
                                                   b1_mu, b1_um,
                                                   nullptr, nullptr, TU, 1, 0);

    // Layer 2: gather fp32 r -> agg image; gemm -> fp32 d_out
    gather_kernel<<<gblocks, 256>>>((const float4*)r_u, (const float4*)r_m);
    tgemm_kernel<<<2 * (TU + TM), 256, SM_TOTAL>>>(iagg_u, iagg_m, ir_u, ir_m,
                                                   b2_mu, b2_um,
                                                   out, out + (size_t)NU * DD, TU, 0, 1);
}

// round 14
// speedup vs baseline: 1.1660x; 1.0977x over previous
#include <cuda_runtime.h>
#include <cuda_bf16.h>
#include <cstdint>

#define NU 100000
#define NM 20000
#define DD 128
#define EE 1000000
#define CAPU 96    // >10 sigma above Poisson(10) max over 100k draws
#define CAPM 256   // >10 sigma above Poisson(50) max over 20k draws
#define TU 782     // ceil(NU/128)
#define TM 157     // ceil(NM/128)
#define BUILD_BLOCKS ((EE + 255) / 256)

// ---------------- scratch (static device globals; no runtime alloc) --------
__device__ int    g_deg_u[NU];
__device__ int    g_deg_m[NM];
__device__ int    g_csr_u[(size_t)NU * CAPU];
__device__ int    g_csr_m[(size_t)NM * CAPM];
__device__ float4 g_r_u[NU * 32];              // layer-1 output (fp32, for gather2)
__device__ float4 g_r_m[NM * 32];
// bf16 hi/lo images, per 128-row tile = 64KB laid out as
// [khalf0: hi 16KB | lo 16KB][khalf1: hi 16KB | lo 16KB];
// within a 16KB plane value (row, klocal) at byte swz128(row*128 + klocal*2).
__device__ uint4 g_ix_u[(size_t)TU * 4096];    // x_user image
__device__ uint4 g_ix_m[(size_t)TM * 4096];    // x_movie image
__device__ uint4 g_iagg_u[(size_t)TU * 4096];  // agg at users
__device__ uint4 g_iagg_m[(size_t)TM * 4096];  // agg at movies
__device__ uint4 g_ir_u[(size_t)TU * 4096];    // layer-1 output image
__device__ uint4 g_ir_m[(size_t)TM * 4096];
// Pre-built mma B fragments, hi/lo MERGED: [matrix][kc][ntile][lane] =
// {hi.k0pair, hi.k8pair, lo.k0pair, lo.k8pair} (canonical m16n8k16 B layout).
__device__ uint4 g_Bfrag[8][8][16][32];

// ---------------- helpers ---------------------------------------------------
__device__ __forceinline__ uint32_t smem_u32(const void* p) {
    uint32_t a;
    asm("{ .reg .u64 t; cvta.to.shared.u64 t, %1; cvt.u32.u64 %0, t; }" : "=r"(a) : "l"(p));
    return a;
}
__device__ __forceinline__ uint32_t pk_bf16x2(float a, float b) {   // {lo=a, hi=b}
    uint32_t r;
    asm("cvt.rn.bf16x2.f32 %0, %1, %2;" : "=r"(r) : "f"(b), "f"(a));
    return r;
}
__device__ __forceinline__ void ldm4(uint32_t* r, uint32_t addr) {
    asm volatile("ldmatrix.sync.aligned.m8n8.x4.shared.b16 {%0,%1,%2,%3}, [%4];"
                 : "=r"(r[0]), "=r"(r[1]), "=r"(r[2]), "=r"(r[3]) : "r"(addr));
}
__device__ __forceinline__ void mma16816(float* c, const uint32_t* a, uint32_t b0, uint32_t b1) {
    asm volatile("mma.sync.aligned.m16n8k16.row.col.f32.bf16.bf16.f32 "
                 "{%0,%1,%2,%3}, {%4,%5,%6,%7}, {%8,%9}, {%0,%1,%2,%3};"
                 : "+f"(c[0]), "+f"(c[1]), "+f"(c[2]), "+f"(c[3])
                 : "r"(a[0]), "r"(a[1]), "r"(a[2]), "r"(a[3]), "r"(b0), "r"(b1));
}
#define CP_ASYNC16(dst, src) asm volatile("cp.async.cg.shared.global [%0], [%1], 16;" :: "r"(dst), "l"(src))
#define CP_COMMIT()          asm volatile("cp.async.commit_group;" ::: "memory")
#define CP_WAIT1()           asm volatile("cp.async.wait_group 1;" ::: "memory")
#define CP_WAIT0()           asm volatile("cp.async.wait_group 0;" ::: "memory")
// swizzle for 128B rows: XOR 16B-chunk bits [4:7) with (row & 7)
__device__ __forceinline__ uint32_t swz128(uint32_t off) { return off ^ ((off >> 3) & 0x70u); }

// ---------------- fused CSR build + xprep ------------------------------------
__global__ __launch_bounds__(256) void build_xprep_kernel(
    const int* __restrict__ src, const int* __restrict__ dst,
    const float* __restrict__ xu, const float* __restrict__ xm)
{
    if ((int)blockIdx.x < BUILD_BLOCKS) {
        int e = blockIdx.x * 256 + threadIdx.x;
        if (e >= EE) return;
        int s = __ldg(src + e);
        int d = __ldg(dst + e);
        int pm = atomicAdd(&g_deg_m[d], 1);
        if (pm < CAPM) g_csr_m[(size_t)d * CAPM + pm] = s;
        int pu = atomicAdd(&g_deg_u[s], 1);
        if (pu < CAPU) g_csr_u[(size_t)s * CAPU + pu] = d;
        return;
    }
    int b = blockIdx.x - BUILD_BLOCKS;
    const bool user = b < TU;
    const int t = user ? b : b - TU;
    const int M = user ? NU : NM;
    const float* X = user ? xu : xm;
    char* img = (char*)((user ? g_ix_u : g_ix_m) + (size_t)t * 4096);

    for (int g = threadIdx.x; g < 2048; g += 256) {
        int row = g >> 4;
        int k = (g & 15) * 8;
        int grow = t * 128 + row;
        if (grow > M - 1) grow = M - 1;
        const float4* src4 = (const float4*)&X[(size_t)grow * 128 + k];
        float4 v0 = __ldg(src4), v1 = __ldg(src4 + 1);
        uint4 hi, lo;
        hi.x = pk_bf16x2(v0.x, v0.y);
        hi.y = pk_bf16x2(v0.z, v0.w);
        hi.z = pk_bf16x2(v1.x, v1.y);
        hi.w = pk_bf16x2(v1.z, v1.w);
        lo.x = pk_bf16x2(v0.x - __uint_as_float(hi.x << 16), v0.y - __uint_as_float(hi.x & 0xFFFF0000u));
        lo.y = pk_bf16x2(v0.z - __uint_as_float(hi.y << 16), v0.w - __uint_as_float(hi.y & 0xFFFF0000u));
        lo.z = pk_bf16x2(v1.x - __uint_as_float(hi.z << 16), v1.y - __uint_as_float(hi.z & 0xFFFF0000u));
        lo.w = pk_bf16x2(v1.z - __uint_as_float(hi.w << 16), v1.w - __uint_as_float(hi.w & 0xFFFF0000u));
        char* plane = img + (k >> 6) * 32768;
        uint32_t so = swz128((uint32_t)row * 128u + (uint32_t)(k & 63) * 2u);
        *(uint4*)(plane + so) = hi;
        *(uint4*)(plane + 16384 + so) = lo;
    }
}

// ---------------- gather: mean of neighbor fp32 rows -> hi/lo image ---------
// One warp per node (R11 form — measured 82.5us/launch).
__global__ __launch_bounds__(256, 6) void gather_kernel(
    const float4* __restrict__ xu, const float4* __restrict__ xm)
{
    const int lane = threadIdx.x & 31;
    const int w = (blockIdx.x * 256 + threadIdx.x) >> 5;

    const int* csr;
    const float4* src;
    char* outImg;
    int deg, row;
    if (w < NU) {
        deg = min(__ldg(&g_deg_u[w]), CAPU);
        csr = &g_csr_u[(size_t)w * CAPU];
        src = xm;
        outImg = (char*)(g_iagg_u + (size_t)(w >> 7) * 4096);
        row = w & 127;
    } else {
        int n = w - NU;
        if (n >= NM) return;
        deg = min(__ldg(&g_deg_m[n]), CAPM);
        csr = &g_csr_m[(size_t)n * CAPM];
        src = xu;
        outImg = (char*)(g_iagg_m + (size_t)(n >> 7) * 4096);
        row = n & 127;
    }

    float4 a0 = make_float4(0.f, 0.f, 0.f, 0.f);
    float4 a1 = make_float4(0.f, 0.f, 0.f, 0.f);

    for (int i = 0; i < deg; i += 32) {
        int idx = (i + lane < deg) ? __ldg(csr + i + lane) : 0;
        int cnt = min(32, deg - i);
        if (cnt == 32) {
#pragma unroll
            for (int j = 0; j < 32; j += 2) {
                int i0 = __shfl_sync(0xffffffffu, idx, j);
                int i1 = __shfl_sync(0xffffffffu, idx, j + 1);
                float4 v0 = __ldg(&src[(size_t)i0 * 32 + lane]);
                float4 v1 = __ldg(&src[(size_t)i1 * 32 + lane]);
                a0.x += v0.x; a0.y += v0.y; a0.z += v0.z; a0.w += v0.w;
                a1.x += v1.x; a1.y += v1.y; a1.z += v1.z; a1.w += v1.w;
            }
        } else {
            for (int j = 0; j < cnt; j++) {
                int id = __shfl_sync(0xffffffffu, idx, j);
                float4 v = __ldg(&src[(size_t)id * 32 + lane]);
                a0.x += v.x; a0.y += v.y; a0.z += v.z; a0.w += v.w;
            }
        }
    }
    float inv = 1.f / (float)max(deg, 1);
    float4 r;
    r.x = (a0.x + a1.x) * inv;
    r.y = (a0.y + a1.y) * inv;
    r.z = (a0.z + a1.z) * inv;
    r.w = (a0.w + a1.w) * inv;

    uint2 hi, lo;
    hi.x = pk_bf16x2(r.x, r.y);
    hi.y = pk_bf16x2(r.z, r.w);
    lo.x = pk_bf16x2(r.x - __uint_as_float(hi.x << 16), r.y - __uint_as_float(hi.x & 0xFFFF0000u));
    lo.y = pk_bf16x2(r.z - __uint_as_float(hi.y << 16), r.w - __uint_as_float(hi.y & 0xFFFF0000u));
    char* plane = outImg + (lane >> 4) * 32768;
    uint32_t so = swz128((uint32_t)row * 128u + (uint32_t)((lane * 8) & 127));
    *(uint2*)(plane + so) = hi;
    *(uint2*)(plane + 16384 + so) = lo;
}

// ---------------- weight prep: canonical B fragments, hi/lo merged ----------
__global__ __launch_bounds__(256) void prep_kernel(
    const float* __restrict__ W0, const float* __restrict__ W1,
    const float* __restrict__ W2, const float* __restrict__ W3,
    const float* __restrict__ W4, const float* __restrict__ W5,
    const float* __restrict__ W6, const float* __restrict__ W7)
{
    const float* Ws[8] = {W0, W1, W2, W3, W4, W5, W6, W7};
    int m = blockIdx.x;
    const float* W = Ws[m];
    for (int idx = threadIdx.x; idx < 4096; idx += 256) {
        int kc = idx >> 9;
        int t = (idx >> 5) & 15;
        int lane = idx & 31;
        int n = t * 8 + (lane >> 2);
        int k0 = kc * 16 + (lane & 3) * 2;
        float w00 = __ldg(&W[(size_t)k0 * 128 + n]);
        float w01 = __ldg(&W[(size_t)(k0 + 1) * 128 + n]);
        float w10 = __ldg(&W[(size_t)(k0 + 8) * 128 + n]);
        float w11 = __ldg(&W[(size_t)(k0 + 9) * 128 + n]);
        uint32_t h0 = pk_bf16x2(w00, w01);
        uint32_t h1 = pk_bf16x2(w10, w11);
        uint32_t l0 = pk_bf16x2(w00 - __uint_as_float(h0 << 16), w01 - __uint_as_float(h0 & 0xFFFF0000u));
        uint32_t l1 = pk_bf16x2(w10 - __uint_as_float(h1 << 16), w11 - __uint_as_float(h1 & 0xFFFF0000u));
        g_Bfrag[m][kc][t][lane] = make_uint4(h0, h1, l0, l1);
    }
}

// ---------------- tensor GEMM: 128x64 CTA tile, 3 CTAs/SM -------------------
// bid = 2*tile + nhalf. 8 warps as 4(M) x 2(N); warp tile 32x32 (acc 32 regs).
// Adjacent CTA pairs share the A tile (L2 reuse). cp.async 2-deep pipeline.
// mode 1: residual x is read from the staged smem image (hi+lo), not global.
#define SM_BIAS 0
#define SM_A    1024
#define SM_TOTAL (1024 + 65536)

__global__ __launch_bounds__(256, 3) void tgemm_kernel(
    const uint4* __restrict__ ia0_u, const uint4* __restrict__ ia0_m,
    const uint4* __restrict__ ia1_u, const uint4* __restrict__ ia1_m,
    const float* __restrict__ b_mu, const float* __restrict__ b_um,
    float* __restrict__ out_u, float* __restrict__ out_m,
    int gb_u, int mode, int layer)
{
    extern __shared__ char smem[];
    const uint32_t sb = smem_u32(smem);
    const int tid = threadIdx.x;
    const int wid = tid >> 5;
    const int lane = tid & 31;

    const int tileg = blockIdx.x >> 1;           // global tile index
    const int nhalf = blockIdx.x & 1;            // which 64-col half
    const bool user = tileg < gb_u;
    const int  tile = user ? tileg : tileg - gb_u;
    const int  base = tile * 128;
    const int  M    = user ? NU : NM;
    const uint4* ia0 = (user ? ia0_u : ia0_m) + (size_t)tile * 4096;  // agg image
    const uint4* ia1 = (user ? ia1_u : ia1_m) + (size_t)tile * 4096;  // x/r image
    const float* bias = user ? b_mu : b_um;
    float* out = user ? out_u : out_m;
    float* rfp = (float*)(user ? g_r_u : g_r_m);
    char* irout = (char*)((user ? g_ir_u : g_ir_m) + (size_t)tile * 4096);
    const int wl_idx = (user ? 2 : 0) + 4 * layer;
    const int wr_idx = wl_idx + 1;

    float* bsm = (float*)(smem + SM_BIAS);
    if (tid < 128) bsm[tid] = __ldg(&bias[tid]);

    const int wm = wid & 3, wn = wid >> 2;       // 4 x 2 warp grid
    const int tbase = nhalf * 8 + wn * 4;        // B ntile base for this warp

    // seg s: pass = s>>1, khalf = s&1 ; source = 32KB at image + khalf*2048 uint4
    auto issue_seg = [&](int s) {
        const uint4* src = ((s >> 1) ? ia1 : ia0) + (s & 1) * 2048;
        const uint32_t dbase = sb + SM_A + (uint32_t)(s & 1) * 32768u + (uint32_t)tid * 16u;
#pragma unroll
        for (int i = 0; i < 8; i++)
            CP_ASYNC16(dbase + (uint32_t)i * 4096u, src + tid + i * 256);
        CP_COMMIT();
    };

    // per-lane ldmatrix A offsets within a 16KB plane (pre-swizzle):
    const int a_row = (lane & 7) + ((lane >> 3) & 1) * 8;
    const int a_kh  = ((lane >> 4) & 1) * 8;
    uint32_t aoff[2];
#pragma unroll
    for (int tm = 0; tm < 2; tm++)
        aoff[tm] = (uint32_t)(wm * 32 + tm * 16 + a_row) * 128u + (uint32_t)a_kh * 2u;

    float acc[2][4][4];
#pragma unroll
    for (int i = 0; i < 2; i++)
#pragma unroll
        for (int j = 0; j < 4; j++)
#pragma unroll
            for (int q = 0; q < 4; q++) acc[i][j][q] = 0.f;

    issue_seg(0);
    issue_seg(1);

    for (int seg = 0; seg < 4; seg++) {
        if (seg < 3) CP_WAIT1(); else CP_WAIT0();
        __syncthreads();

        const int pass = seg >> 1, h = seg & 1;
        const int widx = pass ? wr_idx : wl_idx;
        const uint32_t abase = sb + SM_A + (uint32_t)h * 32768u;
        const uint4* bf = &g_Bfrag[widx][0][tbase][lane];

#pragma unroll
        for (int kcl = 0; kcl < 4; kcl++) {
            const int kc = h * 4 + kcl;
            uint32_t ah[2][4], al[2][4];
#pragma unroll
            for (int tm = 0; tm < 2; tm++) {
                uint32_t so = swz128(aoff[tm] + (uint32_t)kcl * 32u);
                ldm4(ah[tm], abase + so);
                ldm4(al[tm], abase + 16384 + so);
            }
#pragma unroll
            for (int tn = 0; tn < 4; tn++) {
                uint4 b = __ldg(bf + (size_t)kc * 512 + tn * 32);
#pragma unroll
                for (int tm = 0; tm < 2; tm++) {
                    mma16816(acc[tm][tn], ah[tm], b.x, b.y);
                    mma16816(acc[tm][tn], ah[tm], b.z, b.w);
                    mma16816(acc[tm][tn], al[tm], b.x, b.y);
                }
            }
        }
        __syncthreads();
        if (seg < 2) issue_seg(seg + 2);
    }
    // After the loop: buf0 = pass1 khalf0 (k 0..63), buf1 = pass1 khalf1.
    // mode-1 residual x is reconstructed (hi+lo) from these buffers.

    // ---- epilogue ----
    const int gid = lane >> 2, qid = lane & 3;
#pragma unroll
    for (int tm = 0; tm < 2; tm++) {
#pragma unroll
        for (int rs = 0; rs < 2; rs++) {
            int lrow = wm * 32 + tm * 16 + gid + rs * 8;
            int row = base + lrow;
            if (row < M) {
#pragma unroll
                for (int tn = 0; tn < 4; tn++) {
                    int col = nhalf * 64 + wn * 32 + tn * 8 + qid * 2;
                    float vx = acc[tm][tn][rs * 2 + 0] + bsm[col];
                    float vy = acc[tm][tn][rs * 2 + 1] + bsm[col + 1];
                    if (mode) {
                        char* xbuf = smem + SM_A + (col >> 6) * 32768;
                        uint32_t xso = swz128((uint32_t)lrow * 128u + (uint32_t)(col & 63) * 2u);
                        uint32_t xh = *(uint32_t*)(xbuf + xso);
                        uint32_t xl = *(uint32_t*)(xbuf + 16384 + xso);
                        float xvx = __uint_as_float(xh << 16) + __uint_as_float(xl << 16);
                        float xvy = __uint_as_float(xh & 0xFFFF0000u) + __uint_as_float(xl & 0xFFFF0000u);
                        vx = xvx + fmaxf(vx, 0.f);
                        vy = xvy + fmaxf(vy, 0.f);
                        *(float2*)&rfp[(size_t)row * 128 + col] = make_float2(vx, vy);
                        uint32_t hv = pk_bf16x2(vx, vy);
                        uint32_t lv = pk_bf16x2(vx - __uint_as_float(hv << 16),
                                                vy - __uint_as_float(hv & 0xFFFF0000u));
                        char* plane = irout + (col >> 6) * 32768;
                        uint32_t so = swz128((uint32_t)lrow * 128u + (uint32_t)(col & 63) * 2u);
                        *(uint32_t*)(plane + so) = hv;
                        *(uint32_t*)(plane + 16384 + so) = lv;
                    } else {
                        *(float2*)&out[(size_t)row * 128 + col] = make_float2(vx, vy);
                    }
                }
            }
        }
    }
}

// ---------------- host ------------------------------------------------------
extern "C" void kernel_launch(void* const* d_in, const int* in_sizes, int n_in,
                              void* d_out, int out_size)
{
    const float* x_user = nullptr;
    const float* x_movie = nullptr;
    const int* e_src = nullptr;
    const int* e_dst = nullptr;
    const float* W[8] = {};
    const float* B[4] = {};
    int nw = 0, nb = 0;
    for (int i = 0; i < n_in; i++) {
        int sz = in_sizes[i];
        if (sz == NU * DD)      x_user = (const float*)d_in[i];
        else if (sz == NM * DD) x_movie = (const float*)d_in[i];
        else if (sz == EE)      { if (!e_src) e_src = (const int*)d_in[i]; else e_dst = (const int*)d_in[i]; }
        else if (sz == DD * DD) { if (nw < 8) W[nw++] = (const float*)d_in[i]; }
        else if (sz == DD)      { if (nb < 4) B[nb++] = (const float*)d_in[i]; }
    }
    // W order: Wl1_um, Wr1_um, Wl1_mu, Wr1_mu, Wl2_um, Wr2_um, Wl2_mu, Wr2_mu
    const float *b1_um = B[0], *b1_mu = B[1], *b2_um = B[2], *b2_mu = B[3];

    float* out = (float*)d_out;
    int *deg_u, *deg_m;
    float *r_u, *r_m;
    uint4 *ix_u, *ix_m, *iagg_u, *iagg_m, *ir_u, *ir_m;
    cudaGetSymbolAddress((void**)&deg_u, g_deg_u);
    cudaGetSymbolAddress((void**)&deg_m, g_deg_m);
    cudaGetSymbolAddress((void**)&r_u, g_r_u);
    cudaGetSymbolAddress((void**)&r_m, g_r_m);
    cudaGetSymbolAddress((void**)&ix_u, g_ix_u);
    cudaGetSymbolAddress((void**)&ix_m, g_ix_m);
    cudaGetSymbolAddress((void**)&iagg_u, g_iagg_u);
    cudaGetSymbolAddress((void**)&iagg_m, g_iagg_m);
    cudaGetSymbolAddress((void**)&ir_u, g_ir_u);
    cudaGetSymbolAddress((void**)&ir_m, g_ir_m);

    cudaFuncSetAttribute(tgemm_kernel, cudaFuncAttributeMaxDynamicSharedMemorySize, SM_TOTAL);

    const int gblocks = (NU + NM) / 8;          // one warp per node

    prep_kernel<<<8, 256>>>(W[0], W[1], W[2], W[3], W[4], W[5], W[6], W[7]);

    // CSR build + x image prep fused (CSR reused by both layers)
    cudaMemsetAsync(deg_u, 0, NU * sizeof(int));
    cudaMemsetAsync(deg_m, 0, NM * sizeof(int));
    build_xprep_kernel<<<BUILD_BLOCKS + TU + TM, 256>>>(e_src, e_dst, x_user, x_movie);

    // Layer 1: gather fp32 x -> agg image; gemm -> r (fp32 + image)
    gather_kernel<<<gblocks, 256>>>((const float4*)x_user, (const float4*)x_movie);
    tgemm_kernel<<<2 * (TU + TM), 256, SM_TOTAL>>>(iagg_u, iagg_m, ix_u, ix_m,
                                                   b1_mu, b1_um,
                                                   nullptr, nullptr, TU, 1, 0);

    // Layer 2: gather fp32 r -> agg image; gemm -> fp32 d_out
    gather_kernel<<<gblocks, 256>>>((const float4*)r_u, (const float4*)r_m);
    tgemm_kernel<<<2 * (TU + TM), 256, SM_TOTAL>>>(iagg_u, iagg_m, ir_u, ir_m,
                                                   b2_mu, b2_um,
                                                   out, out + (size_t)NU * DD, TU, 0, 1);
}

// round 16
// speedup vs baseline: 1.1929x; 1.0231x over previous
#include <cuda_runtime.h>
#include <cuda_bf16.h>
#include <cstdint>

#define NU 100000
#define NM 20000
#define DD 128
#define EE 1000000
#define CAPU 96    // >10 sigma above Poisson(10) max over 100k draws
#define CAPM 256   // >10 sigma above Poisson(50) max over 20k draws
#define TU 782     // ceil(NU/128)
#define TM 157     // ceil(NM/128)
#define BUILD_BLOCKS ((EE + 255) / 256)

// ---------------- scratch (static device globals; no runtime alloc) --------
__device__ int    g_deg_u[NU];
__device__ int    g_deg_m[NM];
__device__ int    g_csr_u[(size_t)NU * CAPU];
__device__ int    g_csr_m[(size_t)NM * CAPM];
__device__ float4 g_r_u[NU * 32];              // layer-1 output (fp32, for gather2)
__device__ float4 g_r_m[NM * 32];
// bf16 hi/lo images, per 128-row tile = 64KB laid out as
// [khalf0: hi 16KB | lo 16KB][khalf1: hi 16KB | lo 16KB];
// within a 16KB plane value (row, klocal) at byte swz128(row*128 + klocal*2).
__device__ uint4 g_ix_u[(size_t)TU * 4096];    // x_user image
__device__ uint4 g_ix_m[(size_t)TM * 4096];    // x_movie image
__device__ uint4 g_iagg_u[(size_t)TU * 4096];  // agg at users
__device__ uint4 g_iagg_m[(size_t)TM * 4096];  // agg at movies
__device__ uint4 g_ir_u[(size_t)TU * 4096];    // layer-1 output image
__device__ uint4 g_ir_m[(size_t)TM * 4096];
// Pre-built mma B fragments, hi/lo MERGED: [matrix][kc][ntile][lane] =
// {hi.k0pair, hi.k8pair, lo.k0pair, lo.k8pair} (canonical m16n8k16 B layout).
__device__ uint4 g_Bfrag[8][8][16][32];

// ---------------- helpers ---------------------------------------------------
__device__ __forceinline__ uint32_t smem_u32(const void* p) {
    uint32_t a;
    asm("{ .reg .u64 t; cvta.to.shared.u64 t, %1; cvt.u32.u64 %0, t; }" : "=r"(a) : "l"(p));
    return a;
}
__device__ __forceinline__ uint32_t pk_bf16x2(float a, float b) {   // {lo=a, hi=b}
    uint32_t r;
    asm("cvt.rn.bf16x2.f32 %0, %1, %2;" : "=r"(r) : "f"(b), "f"(a));
    return r;
}
__device__ __forceinline__ void ldm4(uint32_t* r, uint32_t addr) {
    asm volatile("ldmatrix.sync.aligned.m8n8.x4.shared.b16 {%0,%1,%2,%3}, [%4];"
                 : "=r"(r[0]), "=r"(r[1]), "=r"(r[2]), "=r"(r[3]) : "r"(addr));
}
__device__ __forceinline__ void mma16816(float* c, const uint32_t* a, uint32_t b0, uint32_t b1) {
    asm volatile("mma.sync.aligned.m16n8k16.row.col.f32.bf16.bf16.f32 "
                 "{%0,%1,%2,%3}, {%4,%5,%6,%7}, {%8,%9}, {%0,%1,%2,%3};"
                 : "+f"(c[0]), "+f"(c[1]), "+f"(c[2]), "+f"(c[3])
                 : "r"(a[0]), "r"(a[1]), "r"(a[2]), "r"(a[3]), "r"(b0), "r"(b1));
}
#define CP_ASYNC16(dst, src) asm volatile("cp.async.cg.shared.global [%0], [%1], 16;" :: "r"(dst), "l"(src))
#define CP_COMMIT()          asm volatile("cp.async.commit_group;" ::: "memory")
#define CP_WAIT1()           asm volatile("cp.async.wait_group 1;" ::: "memory")
#define CP_WAIT0()           asm volatile("cp.async.wait_group 0;" ::: "memory")
// swizzle for 128B rows: XOR 16B-chunk bits [4:7) with (row & 7)
__device__ __forceinline__ uint32_t swz128(uint32_t off) { return off ^ ((off >> 3) & 0x70u); }

// ---------------- fused CSR build + xprep ------------------------------------
__global__ __launch_bounds__(256) void build_xprep_kernel(
    const int* __restrict__ src, const int* __restrict__ dst,
    const float* __restrict__ xu, const float* __restrict__ xm)
{
    if ((int)blockIdx.x < BUILD_BLOCKS) {
        int e = blockIdx.x * 256 + threadIdx.x;
        if (e >= EE) return;
        int s = __ldg(src + e);
        int d = __ldg(dst + e);
        int pm = atomicAdd(&g_deg_m[d], 1);
        if (pm < CAPM) g_csr_m[(size_t)d * CAPM + pm] = s;
        int pu = atomicAdd(&g_deg_u[s], 1);
        if (pu < CAPU) g_csr_u[(size_t)s * CAPU + pu] = d;
        return;
    }
    int b = blockIdx.x - BUILD_BLOCKS;
    const bool user = b < TU;
    const int t = user ? b : b - TU;
    const int M = user ? NU : NM;
    const float* X = user ? xu : xm;
    char* img = (char*)((user ? g_ix_u : g_ix_m) + (size_t)t * 4096);

    for (int g = threadIdx.x; g < 2048; g += 256) {
        int row = g >> 4;
        int k = (g & 15) * 8;
        int grow = t * 128 + row;
        if (grow > M - 1) grow = M - 1;
        const float4* src4 = (const float4*)&X[(size_t)grow * 128 + k];
        float4 v0 = __ldg(src4), v1 = __ldg(src4 + 1);
        uint4 hi, lo;
        hi.x = pk_bf16x2(v0.x, v0.y);
        hi.y = pk_bf16x2(v0.z, v0.w);
        hi.z = pk_bf16x2(v1.x, v1.y);
        hi.w = pk_bf16x2(v1.z, v1.w);
        lo.x = pk_bf16x2(v0.x - __uint_as_float(hi.x << 16), v0.y - __uint_as_float(hi.x & 0xFFFF0000u));
        lo.y = pk_bf16x2(v0.z - __uint_as_float(hi.y << 16), v0.w - __uint_as_float(hi.y & 0xFFFF0000u));
        lo.z = pk_bf16x2(v1.x - __uint_as_float(hi.z << 16), v1.y - __uint_as_float(hi.z & 0xFFFF0000u));
        lo.w = pk_bf16x2(v1.z - __uint_as_float(hi.w << 16), v1.w - __uint_as_float(hi.w & 0xFFFF0000u));
        char* plane = img + (k >> 6) * 32768;
        uint32_t so = swz128((uint32_t)row * 128u + (uint32_t)(k & 63) * 2u);
        *(uint4*)(plane + so) = hi;
        *(uint4*)(plane + 16384 + so) = lo;
    }
}

// ---------------- gather: mean of neighbor fp32 rows -> hi/lo image ---------
// One warp per node; wbase selects the node subrange (user part / movie part).
__global__ __launch_bounds__(256, 6) void gather_kernel(
    const float4* __restrict__ xu, const float4* __restrict__ xm, int wbase)
{
    const int lane = threadIdx.x & 31;
    const int w = wbase + (int)((blockIdx.x * 256 + threadIdx.x) >> 5);

    const int* csr;
    const float4* src;
    char* outImg;
    int deg, row;
    if (w < NU) {
        deg = min(__ldg(&g_deg_u[w]), CAPU);
        csr = &g_csr_u[(size_t)w * CAPU];
        src = xm;
        outImg = (char*)(g_iagg_u + (size_t)(w >> 7) * 4096);
        row = w & 127;
    } else {
        int n = w - NU;
        if (n >= NM) return;
        deg = min(__ldg(&g_deg_m[n]), CAPM);
        csr = &g_csr_m[(size_t)n * CAPM];
        src = xu;
        outImg = (char*)(g_iagg_m + (size_t)(n >> 7) * 4096);
        row = n & 127;
    }

    float4 a0 = make_float4(0.f, 0.f, 0.f, 0.f);
    float4 a1 = make_float4(0.f, 0.f, 0.f, 0.f);

    for (int i = 0; i < deg; i += 32) {
        int idx = (i + lane < deg) ? __ldg(csr + i + lane) : 0;
        int cnt = min(32, deg - i);
        if (cnt == 32) {
#pragma unroll
            for (int j = 0; j < 32; j += 2) {
                int i0 = __shfl_sync(0xffffffffu, idx, j);
                int i1 = __shfl_sync(0xffffffffu, idx, j + 1);
                float4 v0 = __ldg(&src[(size_t)i0 * 32 + lane]);
                float4 v1 = __ldg(&src[(size_t)i1 * 32 + lane]);
                a0.x += v0.x; a0.y += v0.y; a0.z += v0.z; a0.w += v0.w;
                a1.x += v1.x; a1.y += v1.y; a1.z += v1.z; a1.w += v1.w;
            }
        } else {
            for (int j = 0; j < cnt; j++) {
                int id = __shfl_sync(0xffffffffu, idx, j);
                float4 v = __ldg(&src[(size_t)id * 32 + lane]);
                a0.x += v.x; a0.y += v.y; a0.z += v.z; a0.w += v.w;
            }
        }
    }
    float inv = 1.f / (float)max(deg, 1);
    float4 r;
    r.x = (a0.x + a1.x) * inv;
    r.y = (a0.y + a1.y) * inv;
    r.z = (a0.z + a1.z) * inv;
    r.w = (a0.w + a1.w) * inv;

    uint2 hi, lo;
    hi.x = pk_bf16x2(r.x, r.y);
    hi.y = pk_bf16x2(r.z, r.w);
    lo.x = pk_bf16x2(r.x - __uint_as_float(hi.x << 16), r.y - __uint_as_float(hi.x & 0xFFFF0000u));
    lo.y = pk_bf16x2(r.z - __uint_as_float(hi.y << 16), r.w - __uint_as_float(hi.y & 0xFFFF0000u));
    char* plane = outImg + (lane >> 4) * 32768;
    uint32_t so = swz128((uint32_t)row * 128u + (uint32_t)((lane * 8) & 127));
    *(uint2*)(plane + so) = hi;
    *(uint2*)(plane + 16384 + so) = lo;
}

// ---------------- weight prep: canonical B fragments, hi/lo merged ----------
__global__ __launch_bounds__(256) void prep_kernel(
    const float* __restrict__ W0, const float* __restrict__ W1,
    const float* __restrict__ W2, const float* __restrict__ W3,
    const float* __restrict__ W4, const float* __restrict__ W5,
    const float* __restrict__ W6, const float* __restrict__ W7)
{
    const float* Ws[8] = {W0, W1, W2, W3, W4, W5, W6, W7};
    int m = blockIdx.x;
    const float* W = Ws[m];
    for (int idx = threadIdx.x; idx < 4096; idx += 256) {
        int kc = idx >> 9;
        int t = (idx >> 5) & 15;
        int lane = idx & 31;
        int n = t * 8 + (lane >> 2);
        int k0 = kc * 16 + (lane & 3) * 2;
        float w00 = __ldg(&W[(size_t)k0 * 128 + n]);
        float w01 = __ldg(&W[(size_t)(k0 + 1) * 128 + n]);
        float w10 = __ldg(&W[(size_t)(k0 + 8) * 128 + n]);
        float w11 = __ldg(&W[(size_t)(k0 + 9) * 128 + n]);
        uint32_t h0 = pk_bf16x2(w00, w01);
        uint32_t h1 = pk_bf16x2(w10, w11);
        uint32_t l0 = pk_bf16x2(w00 - __uint_as_float(h0 << 16), w01 - __uint_as_float(h0 & 0xFFFF0000u));
        uint32_t l1 = pk_bf16x2(w10 - __uint_as_float(h1 << 16), w11 - __uint_as_float(h1 & 0xFFFF0000u));
        g_Bfrag[m][kc][t][lane] = make_uint4(h0, h1, l0, l1);
    }
}

// ---------------- tensor GEMM: 128x64 CTA tile, 3 CTAs/SM -------------------
// bid = bbase + blockIdx.x = 2*tile + nhalf. 8 warps as 4(M) x 2(N), warp tile
// 32x32. cp.async 2-deep pipeline; mode-1 residual from staged smem image.
#define SM_BIAS 0
#define SM_A    1024
#define SM_TOTAL (1024 + 65536)

__global__ __launch_bounds__(256, 3) void tgemm_kernel(
    const uint4* __restrict__ ia0_u, const uint4* __restrict__ ia0_m,
    const uint4* __restrict__ ia1_u, const uint4* __restrict__ ia1_m,
    const float* __restrict__ b_mu, const float* __restrict__ b_um,
    float* __restrict__ out_u, float* __restrict__ out_m,
    int bbase, int gb_u, int mode, int layer)
{
    extern __shared__ char smem[];
    const uint32_t sb = smem_u32(smem);
    const int tid = threadIdx.x;
    const int wid = tid >> 5;
    const int lane = tid & 31;

    const int bid = (int)blockIdx.x + bbase;
    const int tileg = bid >> 1;                  // global tile index
    const int nhalf = bid & 1;                   // which 64-col half
    const bool user = tileg < gb_u;
    const int  tile = user ? tileg : tileg - gb_u;
    const int  base = tile * 128;
    const int  M    = user ? NU : NM;
    const uint4* ia0 = (user ? ia0_u : ia0_m) + (size_t)tile * 4096;  // agg image
    const uint4* ia1 = (user ? ia1_u : ia1_m) + (size_t)tile * 4096;  // x/r image
    const float* bias = user ? b_mu : b_um;
    float* out = user ? out_u : out_m;
    float* rfp = (float*)(user ? g_r_u : g_r_m);
    char* irout = (char*)((user ? g_ir_u : g_ir_m) + (size_t)tile * 4096);
    const int wl_idx = (user ? 2 : 0) + 4 * layer;
    const int wr_idx = wl_idx + 1;

    float* bsm = (float*)(smem + SM_BIAS);
    if (tid < 128) bsm[tid] = __ldg(&bias[tid]);

    const int wm = wid & 3, wn = wid >> 2;       // 4 x 2 warp grid
    const int tbase = nhalf * 8 + wn * 4;        // B ntile base for this warp

    // seg s: pass = s>>1, khalf = s&1 ; source = 32KB at image + khalf*2048 uint4
    auto issue_seg = [&](int s) {
        const uint4* src = ((s >> 1) ? ia1 : ia0) + (s & 1) * 2048;
        const uint32_t dbase = sb + SM_A + (uint32_t)(s & 1) * 32768u + (uint32_t)tid * 16u;
#pragma unroll
        for (int i = 0; i < 8; i++)
            CP_ASYNC16(dbase + (uint32_t)i * 4096u, src + tid + i * 256);
        CP_COMMIT();
    };

    // per-lane ldmatrix A offsets within a 16KB plane (pre-swizzle):
    const int a_row = (lane & 7) + ((lane >> 3) & 1) * 8;
    const int a_kh  = ((lane >> 4) & 1) * 8;
    uint32_t aoff[2];
#pragma unroll
    for (int tm = 0; tm < 2; tm++)
        aoff[tm] = (uint32_t)(wm * 32 + tm * 16 + a_row) * 128u + (uint32_t)a_kh * 2u;

    float acc[2][4][4];
#pragma unroll
    for (int i = 0; i < 2; i++)
#pragma unroll
        for (int j = 0; j < 4; j++)
#pragma unroll
            for (int q = 0; q < 4; q++) acc[i][j][q] = 0.f;

    issue_seg(0);
    issue_seg(1);

    for (int seg = 0; seg < 4; seg++) {
        if (seg < 3) CP_WAIT1(); else CP_WAIT0();
        __syncthreads();

        const int pass = seg >> 1, h = seg & 1;
        const int widx = pass ? wr_idx : wl_idx;
        const uint32_t abase = sb + SM_A + (uint32_t)h * 32768u;
        const uint4* bf = &g_Bfrag[widx][0][tbase][lane];

#pragma unroll
        for (int kcl = 0; kcl < 4; kcl++) {
            const int kc = h * 4 + kcl;
            uint32_t ah[2][4], al[2][4];
#pragma unroll
            for (int tm = 0; tm < 2; tm++) {
                uint32_t so = swz128(aoff[tm] + (uint32_t)kcl * 32u);
                ldm4(ah[tm], abase + so);
                ldm4(al[tm], abase + 16384 + so);
            }
#pragma unroll
            for (int tn = 0; tn < 4; tn++) {
                uint4 b = __ldg(bf + (size_t)kc * 512 + tn * 32);
#pragma unroll
                for (int tm = 0; tm < 2; tm++) {
                    mma16816(acc[tm][tn], ah[tm], b.x, b.y);
                    mma16816(acc[tm][tn], ah[tm], b.z, b.w);
                    mma16816(acc[tm][tn], al[tm], b.x, b.y);
                }
            }
        }
        __syncthreads();
        if (seg < 2) issue_seg(seg + 2);
    }
    // After the loop: buf0 = pass1 khalf0 (k 0..63), buf1 = pass1 khalf1.
    // mode-1 residual x is reconstructed (hi+lo) from these buffers.

    // ---- epilogue ----
    const int gid = lane >> 2, qid = lane & 3;
#pragma unroll
    for (int tm = 0; tm < 2; tm++) {
#pragma unroll
        for (int rs = 0; rs < 2; rs++) {
            int lrow = wm * 32 + tm * 16 + gid + rs * 8;
            int row = base + lrow;
            if (row < M) {
#pragma unroll
                for (int tn = 0; tn < 4; tn++) {
                    int col = nhalf * 64 + wn * 32 + tn * 8 + qid * 2;
                    float vx = acc[tm][tn][rs * 2 + 0] + bsm[col];
                    float vy = acc[tm][tn][rs * 2 + 1] + bsm[col + 1];
                    if (mode) {
                        char* xbuf = smem + SM_A + (col >> 6) * 32768;
                        uint32_t xso = swz128((uint32_t)lrow * 128u + (uint32_t)(col & 63) * 2u);
                        uint32_t xh = *(uint32_t*)(xbuf + xso);
                        uint32_t xl = *(uint32_t*)(xbuf + 16384 + xso);
                        float xvx = __uint_as_float(xh << 16) + __uint_as_float(xl << 16);
                        float xvy = __uint_as_float(xh & 0xFFFF0000u) + __uint_as_float(xl & 0xFFFF0000u);
                        vx = xvx + fmaxf(vx, 0.f);
                        vy = xvy + fmaxf(vy, 0.f);
                        *(float2*)&rfp[(size_t)row * 128 + col] = make_float2(vx, vy);
                        uint32_t hv = pk_bf16x2(vx, vy);
                        uint32_t lv = pk_bf16x2(vx - __uint_as_float(hv << 16),
                                                vy - __uint_as_float(hv & 0xFFFF0000u));
                        char* plane = irout + (col >> 6) * 32768;
                        uint32_t so = swz128((uint32_t)lrow * 128u + (uint32_t)(col & 63) * 2u);
                        *(uint32_t*)(plane + so) = hv;
                        *(uint32_t*)(plane + 16384 + so) = lv;
                    } else {
                        *(float2*)&out[(size_t)row * 128 + col] = make_float2(vx, vy);
                    }
                }
            }
        }
    }
}

// ---------------- host ------------------------------------------------------
// Streams/events created ONCE (lazy init on the first, non-capturing call).
// The capture call then performs no resource creation, so device memory
// returns exactly to the pre-capture baseline after graph teardown.
static cudaStream_t g_sU = nullptr, g_sM = nullptr;
static cudaEvent_t  g_e0, g_eU1, g_eM1, g_eU2, g_eM2;

extern "C" void kernel_launch(void* const* d_in, const int* in_sizes, int n_in,
                              void* d_out, int out_size)
{
    const float* x_user = nullptr;
    const float* x_movie = nullptr;
    const int* e_src = nullptr;
    const int* e_dst = nullptr;
    const float* W[8] = {};
    const float* B[4] = {};
    int nw = 0, nb = 0;
    for (int i = 0; i < n_in; i++) {
        int sz = in_sizes[i];
        if (sz == NU * DD)      x_user = (const float*)d_in[i];
        else if (sz == NM * DD) x_movie = (const float*)d_in[i];
        else if (sz == EE)      { if (!e_src) e_src = (const int*)d_in[i]; else e_dst = (const int*)d_in[i]; }
        else if (sz == DD * DD) { if (nw < 8) W[nw++] = (const float*)d_in[i]; }
        else if (sz == DD)      { if (nb < 4) B[nb++] = (const float*)d_in[i]; }
    }
    // W order: Wl1_um, Wr1_um, Wl1_mu, Wr1_mu, Wl2_um, Wr2_um, Wl2_mu, Wr2_mu
    const float *b1_um = B[0], *b1_mu = B[1], *b2_um = B[2], *b2_mu = B[3];

    float* out = (float*)d_out;
    int *deg_u, *deg_m;
    float *r_u, *r_m;
    uint4 *ix_u, *ix_m, *iagg_u, *iagg_m, *ir_u, *ir_m;
    cudaGetSymbolAddress((void**)&deg_u, g_deg_u);
    cudaGetSymbolAddress((void**)&deg_m, g_deg_m);
    cudaGetSymbolAddress((void**)&r_u, g_r_u);
    cudaGetSymbolAddress((void**)&r_m, g_r_m);
    cudaGetSymbolAddress((void**)&ix_u, g_ix_u);
    cudaGetSymbolAddress((void**)&ix_m, g_ix_m);
    cudaGetSymbolAddress((void**)&iagg_u, g_iagg_u);
    cudaGetSymbolAddress((void**)&iagg_m, g_iagg_m);
    cudaGetSymbolAddress((void**)&ir_u, g_ir_u);
    cudaGetSymbolAddress((void**)&ir_m, g_ir_m);

    cudaFuncSetAttribute(tgemm_kernel, cudaFuncAttributeMaxDynamicSharedMemorySize, SM_TOTAL);

    if (!g_sU) {
        cudaStreamCreateWithFlags(&g_sU, cudaStreamNonBlocking);
        cudaStreamCreateWithFlags(&g_sM, cudaStreamNonBlocking);
        cudaEventCreateWithFlags(&g_e0,  cudaEventDisableTiming);
        cudaEventCreateWithFlags(&g_eU1, cudaEventDisableTiming);
        cudaEventCreateWithFlags(&g_eM1, cudaEventDisableTiming);
        cudaEventCreateWithFlags(&g_eU2, cudaEventDisableTiming);
        cudaEventCreateWithFlags(&g_eM2, cudaEventDisableTiming);
    }
    cudaStream_t sU = g_sU, sM = g_sM;

    // ---- common prologue on the capture-origin stream ----
    prep_kernel<<<8, 256>>>(W[0], W[1], W[2], W[3], W[4], W[5], W[6], W[7]);
    cudaMemsetAsync(deg_u, 0, NU * sizeof(int));
    cudaMemsetAsync(deg_m, 0, NM * sizeof(int));
    build_xprep_kernel<<<BUILD_BLOCKS + TU + TM, 256>>>(e_src, e_dst, x_user, x_movie);
    cudaEventRecord(g_e0, 0);
    cudaStreamWaitEvent(sU, g_e0, 0);
    cudaStreamWaitEvent(sM, g_e0, 0);

    // ---- user pipeline (stream U) ----
    gather_kernel<<<NU / 8, 256, 0, sU>>>((const float4*)x_user, (const float4*)x_movie, 0);
    tgemm_kernel<<<2 * TU, 256, SM_TOTAL, sU>>>(iagg_u, iagg_m, ix_u, ix_m,
                                                b1_mu, b1_um, nullptr, nullptr,
                                                0, TU, 1, 0);
    cudaEventRecord(g_eU1, sU);

    // ---- movie pipeline (stream M) ----
    gather_kernel<<<NM / 8, 256, 0, sM>>>((const float4*)x_user, (const float4*)x_movie, NU);
    tgemm_kernel<<<2 * TM, 256, SM_TOTAL, sM>>>(iagg_u, iagg_m, ix_u, ix_m,
                                                b1_mu, b1_um, nullptr, nullptr,
                                                2 * TU, TU, 1, 0);
    cudaEventRecord(g_eM1, sM);

    // ---- layer 2 ----
    // gather2_u reads r_m (produced by movie tgemm1) -> wait eM1
    cudaStreamWaitEvent(sU, g_eM1, 0);
    gather_kernel<<<NU / 8, 256, 0, sU>>>((const float4*)r_u, (const float4*)r_m, 0);
    tgemm_kernel<<<2 * TU, 256, SM_TOTAL, sU>>>(iagg_u, iagg_m, ir_u, ir_m,
                                                b2_mu, b2_um, out, out + (size_t)NU * DD,
                                                0, TU, 0, 1);
    cudaEventRecord(g_eU2, sU);

    // gather2_m reads r_u (produced by user tgemm1) -> wait eU1
    cudaStreamWaitEvent(sM, g_eU1, 0);
    gather_kernel<<<NM / 8, 256, 0, sM>>>((const float4*)r_u, (const float4*)r_m, NU);
    tgemm_kernel<<<2 * TM, 256, SM_TOTAL, sM>>>(iagg_u, iagg_m, ir_u, ir_m,
                                                b2_mu, b2_um, out, out + (size_t)NU * DD,
                                                2 * TU, TU, 0, 1);
    cudaEventRecord(g_eM2, sM);

    // ---- join back onto the capture-origin stream ----
    cudaStreamWaitEvent(0, g_eU2, 0);
    cudaStreamWaitEvent(0, g_eM2, 0);
}

// round 17
// speedup vs baseline: 1.2408x; 1.0401x over previous
#include <cuda_runtime.h>
#include <cuda_bf16.h>
#include <cstdint>

#define NU 100000
#define NM 20000
#define DD 128
#define EE 1000000
#define CAPU 96    // >10 sigma above Poisson(10) max over 100k draws
#define CAPM 256   // >10 sigma above Poisson(50) max over 20k draws
#define TU 782     // ceil(NU/128)
#define TM 157     // ceil(NM/128)
#define BUILD_BLOCKS ((EE + 255) / 256)

// ---------------- scratch (static device globals; no runtime alloc) --------
__device__ int    g_deg_u[NU];
__device__ int    g_deg_m[NM];
__device__ int    g_csr_u[(size_t)NU * CAPU];
__device__ int    g_csr_m[(size_t)NM * CAPM];
__device__ float4 g_r_u[NU * 32];              // layer-1 output (fp32, for gather2)
__device__ float4 g_r_m[NM * 32];
// bf16 hi/lo images, per 128-row tile = 64KB: [kh0 hi|kh0 lo|kh1 hi|kh1 lo]
// 16KB planes; value (row,klocal) at byte swz128(row*128 + klocal*2).
__device__ uint4 g_ix_u[(size_t)TU * 4096];     // x_user image
__device__ uint4 g_ix_m[(size_t)TM * 4096];     // x_movie image
__device__ uint4 g_iagg_u[(size_t)TU * 4096];   // layer-1 agg at users
__device__ uint4 g_iagg_m[(size_t)TM * 4096];   // layer-1 agg at movies
__device__ uint4 g_iagg2_u[(size_t)TU * 4096];  // layer-2 agg (double buffer)
__device__ uint4 g_iagg2_m[(size_t)TM * 4096];
__device__ uint4 g_ir_u[(size_t)TU * 4096];     // layer-1 output image
__device__ uint4 g_ir_m[(size_t)TM * 4096];
// Pre-built mma B fragments, hi/lo MERGED: [matrix][kc][ntile][lane].
__device__ uint4 g_Bfrag[8][8][16][32];

// ---------------- helpers ---------------------------------------------------
__device__ __forceinline__ uint32_t smem_u32(const void* p) {
    uint32_t a;
    asm("{ .reg .u64 t; cvta.to.shared.u64 t, %1; cvt.u32.u64 %0, t; }" : "=r"(a) : "l"(p));
    return a;
}
__device__ __forceinline__ uint32_t pk_bf16x2(float a, float b) {   // {lo=a, hi=b}
    uint32_t r;
    asm("cvt.rn.bf16x2.f32 %0, %1, %2;" : "=r"(r) : "f"(b), "f"(a));
    return r;
}
__device__ __forceinline__ void ldm4(uint32_t* r, uint32_t addr) {
    asm volatile("ldmatrix.sync.aligned.m8n8.x4.shared.b16 {%0,%1,%2,%3}, [%4];"
                 : "=r"(r[0]), "=r"(r[1]), "=r"(r[2]), "=r"(r[3]) : "r"(addr));
}
__device__ __forceinline__ void mma16816(float* c, const uint32_t* a, uint32_t b0, uint32_t b1) {
    asm volatile("mma.sync.aligned.m16n8k16.row.col.f32.bf16.bf16.f32 "
                 "{%0,%1,%2,%3}, {%4,%5,%6,%7}, {%8,%9}, {%0,%1,%2,%3};"
                 : "+f"(c[0]), "+f"(c[1]), "+f"(c[2]), "+f"(c[3])
                 : "r"(a[0]), "r"(a[1]), "r"(a[2]), "r"(a[3]), "r"(b0), "r"(b1));
}
#define CP_ASYNC16(dst, src) asm volatile("cp.async.cg.shared.global [%0], [%1], 16;" :: "r"(dst), "l"(src))
#define CP_COMMIT()          asm volatile("cp.async.commit_group;" ::: "memory")
#define CP_WAIT1()           asm volatile("cp.async.wait_group 1;" ::: "memory")
#define CP_WAIT0()           asm volatile("cp.async.wait_group 0;" ::: "memory")
__device__ __forceinline__ uint32_t swz128(uint32_t off) { return off ^ ((off >> 3) & 0x70u); }

// ---------------- CSR build --------------------------------------------------
__global__ __launch_bounds__(256) void build_kernel(
    const int* __restrict__ src, const int* __restrict__ dst)
{
    int e = blockIdx.x * 256 + threadIdx.x;
    if (e >= EE) return;
    int s = __ldg(src + e);
    int d = __ldg(dst + e);
    int pm = atomicAdd(&g_deg_m[d], 1);
    if (pm < CAPM) g_csr_m[(size_t)d * CAPM + pm] = s;
    int pu = atomicAdd(&g_deg_u[s], 1);
    if (pu < CAPU) g_csr_u[(size_t)s * CAPU + pu] = d;
}

// ---------------- xprep: fp32 features -> hi/lo bf16 image -------------------
__global__ __launch_bounds__(256) void xprep_kernel(
    const float* __restrict__ xu, const float* __restrict__ xm)
{
    const bool user = (int)blockIdx.x < TU;
    const int t = user ? blockIdx.x : blockIdx.x - TU;
    const int M = user ? NU : NM;
    const float* X = user ? xu : xm;
    char* img = (char*)((user ? g_ix_u : g_ix_m) + (size_t)t * 4096);

    for (int g = threadIdx.x; g < 2048; g += 256) {
        int row = g >> 4;
        int k = (g & 15) * 8;
        int grow = t * 128 + row;
        if (grow > M - 1) grow = M - 1;
        const float4* src4 = (const float4*)&X[(size_t)grow * 128 + k];
        float4 v0 = __ldg(src4), v1 = __ldg(src4 + 1);
        uint4 hi, lo;
        hi.x = pk_bf16x2(v0.x, v0.y);
        hi.y = pk_bf16x2(v0.z, v0.w);
        hi.z = pk_bf16x2(v1.x, v1.y);
        hi.w = pk_bf16x2(v1.z, v1.w);
        lo.x = pk_bf16x2(v0.x - __uint_as_float(hi.x << 16), v0.y - __uint_as_float(hi.x & 0xFFFF0000u));
        lo.y = pk_bf16x2(v0.z - __uint_as_float(hi.y << 16), v0.w - __uint_as_float(hi.y & 0xFFFF0000u));
        lo.z = pk_bf16x2(v1.x - __uint_as_float(hi.z << 16), v1.y - __uint_as_float(hi.z & 0xFFFF0000u));
        lo.w = pk_bf16x2(v1.z - __uint_as_float(hi.w << 16), v1.w - __uint_as_float(hi.w & 0xFFFF0000u));
        char* plane = img + (k >> 6) * 32768;
        uint32_t so = swz128((uint32_t)row * 128u + (uint32_t)(k & 63) * 2u);
        *(uint4*)(plane + so) = hi;
        *(uint4*)(plane + 16384 + so) = lo;
    }
}

// ---------------- gather: mean of neighbor fp32 rows -> hi/lo image ---------
// One warp per node; wbase selects node subrange; agg* select output buffer.
__global__ __launch_bounds__(256, 6) void gather_kernel(
    const float4* __restrict__ xu, const float4* __restrict__ xm, int wbase,
    uint4* __restrict__ aggu, uint4* __restrict__ aggm)
{
    const int lane = threadIdx.x & 31;
    const int w = wbase + (int)((blockIdx.x * 256 + threadIdx.x) >> 5);

    const int* csr;
    const float4* src;
    char* outImg;
    int deg, row;
    if (w < NU) {
        deg = min(__ldg(&g_deg_u[w]), CAPU);
        csr = &g_csr_u[(size_t)w * CAPU];
        src = xm;
        outImg = (char*)(aggu + (size_t)(w >> 7) * 4096);
        row = w & 127;
    } else {
        int n = w - NU;
        if (n >= NM) return;
        deg = min(__ldg(&g_deg_m[n]), CAPM);
        csr = &g_csr_m[(size_t)n * CAPM];
        src = xu;
        outImg = (char*)(aggm + (size_t)(n >> 7) * 4096);
        row = n & 127;
    }

    float4 a0 = make_float4(0.f, 0.f, 0.f, 0.f);
    float4 a1 = make_float4(0.f, 0.f, 0.f, 0.f);

    for (int i = 0; i < deg; i += 32) {
        int idx = (i + lane < deg) ? __ldg(csr + i + lane) : 0;
        int cnt = min(32, deg - i);
        if (cnt == 32) {
#pragma unroll
            for (int j = 0; j < 32; j += 2) {
                int i0 = __shfl_sync(0xffffffffu, idx, j);
                int i1 = __shfl_sync(0xffffffffu, idx, j + 1);
                float4 v0 = __ldg(&src[(size_t)i0 * 32 + lane]);
                float4 v1 = __ldg(&src[(size_t)i1 * 32 + lane]);
                a0.x += v0.x; a0.y += v0.y; a0.z += v0.z; a0.w += v0.w;
                a1.x += v1.x; a1.y += v1.y; a1.z += v1.z; a1.w += v1.w;
            }
        } else {
            for (int j = 0; j < cnt; j++) {
                int id = __shfl_sync(0xffffffffu, idx, j);
                float4 v = __ldg(&src[(size_t)id * 32 + lane]);
                a0.x += v.x; a0.y += v.y; a0.z += v.z; a0.w += v.w;
            }
        }
    }
    float inv = 1.f / (float)max(deg, 1);
    float4 r;
    r.x = (a0.x + a1.x) * inv;
    r.y = (a0.y + a1.y) * inv;
    r.z = (a0.z + a1.z) * inv;
    r.w = (a0.w + a1.w) * inv;

    uint2 hi, lo;
    hi.x = pk_bf16x2(r.x, r.y);
    hi.y = pk_bf16x2(r.z, r.w);
    lo.x = pk_bf16x2(r.x - __uint_as_float(hi.x << 16), r.y - __uint_as_float(hi.x & 0xFFFF0000u));
    lo.y = pk_bf16x2(r.z - __uint_as_float(hi.y << 16), r.w - __uint_as_float(hi.y & 0xFFFF0000u));
    char* plane = outImg + (lane >> 4) * 32768;
    uint32_t so = swz128((uint32_t)row * 128u + (uint32_t)((lane * 8) & 127));
    *(uint2*)(plane + so) = hi;
    *(uint2*)(plane + 16384 + so) = lo;
}

// ---------------- weight prep: canonical B fragments, hi/lo merged ----------
__global__ __launch_bounds__(256) void prep_kernel(
    const float* __restrict__ W0, const float* __restrict__ W1,
    const float* __restrict__ W2, const float* __restrict__ W3,
    const float* __restrict__ W4, const float* __restrict__ W5,
    const float* __restrict__ W6, const float* __restrict__ W7)
{
    const float* Ws[8] = {W0, W1, W2, W3, W4, W5, W6, W7};
    int m = blockIdx.x;
    const float* W = Ws[m];
    for (int idx = threadIdx.x; idx < 4096; idx += 256) {
        int kc = idx >> 9;
        int t = (idx >> 5) & 15;
        int lane = idx & 31;
        int n = t * 8 + (lane >> 2);
        int k0 = kc * 16 + (lane & 3) * 2;
        float w00 = __ldg(&W[(size_t)k0 * 128 + n]);
        float w01 = __ldg(&W[(size_t)(k0 + 1) * 128 + n]);
        float w10 = __ldg(&W[(size_t)(k0 + 8) * 128 + n]);
        float w11 = __ldg(&W[(size_t)(k0 + 9) * 128 + n]);
        uint32_t h0 = pk_bf16x2(w00, w01);
        uint32_t h1 = pk_bf16x2(w10, w11);
        uint32_t l0 = pk_bf16x2(w00 - __uint_as_float(h0 << 16), w01 - __uint_as_float(h0 & 0xFFFF0000u));
        uint32_t l1 = pk_bf16x2(w10 - __uint_as_float(h1 << 16), w11 - __uint_as_float(h1 & 0xFFFF0000u));
        g_Bfrag[m][kc][t][lane] = make_uint4(h0, h1, l0, l1);
    }
}

// ---------------- tensor GEMM: 128x64 CTA tile, 3 CTAs/SM -------------------
#define SM_BIAS 0
#define SM_A    1024
#define SM_TOTAL (1024 + 65536)

__global__ __launch_bounds__(256, 3) void tgemm_kernel(
    const uint4* __restrict__ ia0_u, const uint4* __restrict__ ia0_m,
    const uint4* __restrict__ ia1_u, const uint4* __restrict__ ia1_m,
    const float* __restrict__ b_mu, const float* __restrict__ b_um,
    float* __restrict__ out_u, float* __restrict__ out_m,
    int bbase, int gb_u, int mode, int layer)
{
    extern __shared__ char smem[];
    const uint32_t sb = smem_u32(smem);
    const int tid = threadIdx.x;
    const int wid = tid >> 5;
    const int lane = tid & 31;

    const int bid = (int)blockIdx.x + bbase;
    const int tileg = bid >> 1;
    const int nhalf = bid & 1;
    const bool user = tileg < gb_u;
    const int  tile = user ? tileg : tileg - gb_u;
    const int  base = tile * 128;
    const int  M    = user ? NU : NM;
    const uint4* ia0 = (user ? ia0_u : ia0_m) + (size_t)tile * 4096;
    const uint4* ia1 = (user ? ia1_u : ia1_m) + (size_t)tile * 4096;
    const float* bias = user ? b_mu : b_um;
    float* out = user ? out_u : out_m;
    float* rfp = (float*)(user ? g_r_u : g_r_m);
    char* irout = (char*)((user ? g_ir_u : g_ir_m) + (size_t)tile * 4096);
    const int wl_idx = (user ? 2 : 0) + 4 * layer;
    const int wr_idx = wl_idx + 1;

    float* bsm = (float*)(smem + SM_BIAS);
    if (tid < 128) bsm[tid] = __ldg(&bias[tid]);

    const int wm = wid & 3, wn = wid >> 2;
    const int tbase = nhalf * 8 + wn * 4;

    auto issue_seg = [&](int s) {
        const uint4* src = ((s >> 1) ? ia1 : ia0) + (s & 1) * 2048;
        const uint32_t dbase = sb + SM_A + (uint32_t)(s & 1) * 32768u + (uint32_t)tid * 16u;
#pragma unroll
        for (int i = 0; i < 8; i++)
            CP_ASYNC16(dbase + (uint32_t)i * 4096u, src + tid + i * 256);
        CP_COMMIT();
    };

    const int a_row = (lane & 7) + ((lane >> 3) & 1) * 8;
    const int a_kh  = ((lane >> 4) & 1) * 8;
    uint32_t aoff[2];
#pragma unroll
    for (int tm = 0; tm < 2; tm++)
        aoff[tm] = (uint32_t)(wm * 32 + tm * 16 + a_row) * 128u + (uint32_t)a_kh * 2u;

    float acc[2][4][4];
#pragma unroll
    for (int i = 0; i < 2; i++)
#pragma unroll
        for (int j = 0; j < 4; j++)
#pragma unroll
            for (int q = 0; q < 4; q++) acc[i][j][q] = 0.f;

    issue_seg(0);
    issue_seg(1);

    for (int seg = 0; seg < 4; seg++) {
        if (seg < 3) CP_WAIT1(); else CP_WAIT0();
        __syncthreads();

        const int pass = seg >> 1, h = seg & 1;
        const int widx = pass ? wr_idx : wl_idx;
        const uint32_t abase = sb + SM_A + (uint32_t)h * 32768u;
        const uint4* bf = &g_Bfrag[widx][0][tbase][lane];

#pragma unroll
        for (int kcl = 0; kcl < 4; kcl++) {
            const int kc = h * 4 + kcl;
            uint32_t ah[2][4], al[2][4];
#pragma unroll
            for (int tm = 0; tm < 2; tm++) {
                uint32_t so = swz128(aoff[tm] + (uint32_t)kcl * 32u);
                ldm4(ah[tm], abase + so);
                ldm4(al[tm], abase + 16384 + so);
            }
#pragma unroll
            for (int tn = 0; tn < 4; tn++) {
                uint4 b = __ldg(bf + (size_t)kc * 512 + tn * 32);
#pragma unroll
                for (int tm = 0; tm < 2; tm++) {
                    mma16816(acc[tm][tn], ah[tm], b.x, b.y);
                    mma16816(acc[tm][tn], ah[tm], b.z, b.w);
                    mma16816(acc[tm][tn], al[tm], b.x, b.y);
                }
            }
        }
        __syncthreads();
        if (seg < 2) issue_seg(seg + 2);
    }
    // buf0/buf1 now hold pass-1 A (x/r image) -> mode-1 residual source.

    const int gid = lane >> 2, qid = lane & 3;
#pragma unroll
    for (int tm = 0; tm < 2; tm++) {
#pragma unroll
        for (int rs = 0; rs < 2; rs++) {
            int lrow = wm * 32 + tm * 16 + gid + rs * 8;
            int row = base + lrow;
            if (row < M) {
#pragma unroll
                for (int tn = 0; tn < 4; tn++) {
                    int col = nhalf * 64 + wn * 32 + tn * 8 + qid * 2;
                    float vx = acc[tm][tn][rs * 2 + 0] + bsm[col];
                    float vy = acc[tm][tn][rs * 2 + 1] + bsm[col + 1];
                    if (mode) {
                        char* xbuf = smem + SM_A + (col >> 6) * 32768;
                        uint32_t xso = swz128((uint32_t)lrow * 128u + (uint32_t)(col & 63) * 2u);
                        uint32_t xh = *(uint32_t*)(xbuf + xso);
                        uint32_t xl = *(uint32_t*)(xbuf + 16384 + xso);
                        float xvx = __uint_as_float(xh << 16) + __uint_as_float(xl << 16);
                        float xvy = __uint_as_float(xh & 0xFFFF0000u) + __uint_as_float(xl & 0xFFFF0000u);
                        vx = xvx + fmaxf(vx, 0.f);
                        vy = xvy + fmaxf(vy, 0.f);
                        *(float2*)&rfp[(size_t)row * 128 + col] = make_float2(vx, vy);
                        uint32_t hv = pk_bf16x2(vx, vy);
                        uint32_t lv = pk_bf16x2(vx - __uint_as_float(hv << 16),
                                                vy - __uint_as_float(hv & 0xFFFF0000u));
                        char* plane = irout + (col >> 6) * 32768;
                        uint32_t so = swz128((uint32_t)lrow * 128u + (uint32_t)(col & 63) * 2u);
                        *(uint32_t*)(plane + so) = hv;
                        *(uint32_t*)(plane + 16384 + so) = lv;
                    } else {
                        *(float2*)&out[(size_t)row * 128 + col] = make_float2(vx, vy);
                    }
                }
            }
        }
    }
}

// ---------------- host ------------------------------------------------------
// Streams/events created ONCE (lazy init on the first, non-capturing call);
// the capture call performs no resource creation.
static cudaStream_t g_sU = nullptr, g_sM = nullptr, g_sX = nullptr;
static cudaEvent_t  g_e00, g_e0, g_eX, g_eU1, g_eM1, g_eG2U, g_eU2, g_eM2;

extern "C" void kernel_launch(void* const* d_in, const int* in_sizes, int n_in,
                              void* d_out, int out_size)
{
    const float* x_user = nullptr;
    const float* x_movie = nullptr;
    const int* e_src = nullptr;
    const int* e_dst = nullptr;
    const float* W[8] = {};
    const float* B[4] = {};
    int nw = 0, nb = 0;
    for (int i = 0; i < n_in; i++) {
        int sz = in_sizes[i];
        if (sz == NU * DD)      x_user = (const float*)d_in[i];
        else if (sz == NM * DD) x_movie = (const float*)d_in[i];
        else if (sz == EE)      { if (!e_src) e_src = (const int*)d_in[i]; else e_dst = (const int*)d_in[i]; }
        else if (sz == DD * DD) { if (nw < 8) W[nw++] = (const float*)d_in[i]; }
        else if (sz == DD)      { if (nb < 4) B[nb++] = (const float*)d_in[i]; }
    }
    // W order: Wl1_um, Wr1_um, Wl1_mu, Wr1_mu, Wl2_um, Wr2_um, Wl2_mu, Wr2_mu
    const float *b1_um = B[0], *b1_mu = B[1], *b2_um = B[2], *b2_mu = B[3];

    float* out = (float*)d_out;
    int *deg_u, *deg_m;
    float *r_u, *r_m;
    uint4 *ix_u, *ix_m, *iagg_u, *iagg_m, *iagg2_u, *iagg2_m, *ir_u, *ir_m;
    cudaGetSymbolAddress((void**)&deg_u, g_deg_u);
    cudaGetSymbolAddress((void**)&deg_m, g_deg_m);
    cudaGetSymbolAddress((void**)&r_u, g_r_u);
    cudaGetSymbolAddress((void**)&r_m, g_r_m);
    cudaGetSymbolAddress((void**)&ix_u, g_ix_u);
    cudaGetSymbolAddress((void**)&ix_m, g_ix_m);
    cudaGetSymbolAddress((void**)&iagg_u, g_iagg_u);
    cudaGetSymbolAddress((void**)&iagg_m, g_iagg_m);
    cudaGetSymbolAddress((void**)&iagg2_u, g_iagg2_u);
    cudaGetSymbolAddress((void**)&iagg2_m, g_iagg2_m);
    cudaGetSymbolAddress((void**)&ir_u, g_ir_u);
    cudaGetSymbolAddress((void**)&ir_m, g_ir_m);

    cudaFuncSetAttribute(tgemm_kernel, cudaFuncAttributeMaxDynamicSharedMemorySize, SM_TOTAL);

    if (!g_sU) {
        cudaStreamCreateWithFlags(&g_sU, cudaStreamNonBlocking);
        cudaStreamCreateWithFlags(&g_sM, cudaStreamNonBlocking);
        cudaStreamCreateWithFlags(&g_sX, cudaStreamNonBlocking);
        cudaEventCreateWithFlags(&g_e00, cudaEventDisableTiming);
        cudaEventCreateWithFlags(&g_e0,  cudaEventDisableTiming);
        cudaEventCreateWithFlags(&g_eX,  cudaEventDisableTiming);
        cudaEventCreateWithFlags(&g_eU1, cudaEventDisableTiming);
        cudaEventCreateWithFlags(&g_eM1, cudaEventDisableTiming);
        cudaEventCreateWithFlags(&g_eG2U, cudaEventDisableTiming);
        cudaEventCreateWithFlags(&g_eU2, cudaEventDisableTiming);
        cudaEventCreateWithFlags(&g_eM2, cudaEventDisableTiming);
    }
    cudaStream_t sU = g_sU, sM = g_sM, sX = g_sX;

    // ---- fork point ----
    cudaEventRecord(g_e00, 0);
    cudaStreamWaitEvent(sX, g_e00, 0);

    // stream 0: CSR build (gathers depend on this)
    cudaMemsetAsync(deg_u, 0, NU * sizeof(int));
    cudaMemsetAsync(deg_m, 0, NM * sizeof(int));
    build_kernel<<<BUILD_BLOCKS, 256>>>(e_src, e_dst);
    cudaEventRecord(g_e0, 0);
    cudaStreamWaitEvent(sU, g_e0, 0);
    cudaStreamWaitEvent(sM, g_e0, 0);

    // stream X: weight prep + x images (independent of build; tgemm1 deps)
    prep_kernel<<<8, 256, 0, sX>>>(W[0], W[1], W[2], W[3], W[4], W[5], W[6], W[7]);
    xprep_kernel<<<TU + TM, 256, 0, sX>>>(x_user, x_movie);
    cudaEventRecord(g_eX, sX);

    // ---- layer 1, user pipeline (stream U) ----
    gather_kernel<<<NU / 8, 256, 0, sU>>>((const float4*)x_user, (const float4*)x_movie, 0,
                                          iagg_u, iagg_m);
    cudaStreamWaitEvent(sU, g_eX, 0);
    tgemm_kernel<<<2 * TU, 256, SM_TOTAL, sU>>>(iagg_u, iagg_m, ix_u, ix_m,
                                                b1_mu, b1_um, nullptr, nullptr,
                                                0, TU, 1, 0);
    cudaEventRecord(g_eU1, sU);

    // ---- layer 1, movie pipeline (stream M) ----
    gather_kernel<<<NM / 8, 256, 0, sM>>>((const float4*)x_user, (const float4*)x_movie, NU,
                                          iagg_u, iagg_m);
    cudaStreamWaitEvent(sM, g_eX, 0);
    tgemm_kernel<<<2 * TM, 256, SM_TOTAL, sM>>>(iagg_u, iagg_m, ix_u, ix_m,
                                                b1_mu, b1_um, nullptr, nullptr,
                                                2 * TU, TU, 1, 0);
    cudaEventRecord(g_eM1, sM);

    // ---- layer 2 ----
    // gather2_u needs only r_m (movie tgemm1) -> runs on sX concurrent with
    // tgemm1_u, writing the double buffer iagg2 (no WAR on iagg).
    cudaStreamWaitEvent(sX, g_eM1, 0);
    gather_kernel<<<NU / 8, 256, 0, sX>>>((const float4*)r_u, (const float4*)r_m, 0,
                                          iagg2_u, iagg2_m);
    cudaEventRecord(g_eG2U, sX);

    cudaStreamWaitEvent(sU, g_eG2U, 0);
    tgemm_kernel<<<2 * TU, 256, SM_TOTAL, sU>>>(iagg2_u, iagg2_m, ir_u, ir_m,
                                                b2_mu, b2_um, out, out + (size_t)NU * DD,
                                                0, TU, 0, 1);
    cudaEventRecord(g_eU2, sU);

    // gather2_m needs r_u (user tgemm1) -> stream M waits eU1
    cudaStreamWaitEvent(sM, g_eU1, 0);
    gather_kernel<<<NM / 8, 256, 0, sM>>>((const float4*)r_u, (const float4*)r_m, NU,
                                          iagg2_u, iagg2_m);
    tgemm_kernel<<<2 * TM, 256, SM_TOTAL, sM>>>(iagg2_u, iagg2_m, ir_u, ir_m,
                                                b2_mu, b2_um, out, out + (size_t)NU * DD,
                                                2 * TU, TU, 0, 1);
    cudaEventRecord(g_eM2, sM);

    // ---- join ----
    cudaStreamWaitEvent(0, g_eU2, 0);
    cudaStreamWaitEvent(0, g_eM2, 0);
}